// round 1
// baseline (speedup 1.0000x reference)
#include <cuda_runtime.h>
#include <math.h>

#define NN 50000
#define NE 800000
#define ND 64
#define ED 32
#define NH 128
#define OD 32
#define NL 3
#define NG 128

// ---------------- device scratch (globals: no allocation allowed) ----------------
__device__ float g_h[NN * ND];            // current node features
__device__ float g_hd[NN * ND];           // h @ W_dense
__device__ float g_msg[(size_t)NE * ND];  // per-edge messages (204.8 MB)
__device__ float g_score[NE];
__device__ float g_expw[NE];
__device__ float g_segmax[NN];
__device__ float g_denom[NN];
__device__ float g_agg[NN * ND];
__device__ float g_pooled[NG * ND];
__device__ int   g_cnt[NG];

__device__ __forceinline__ void atomicMaxF(float* a, float v) {
    // float max via integer atomics (works across mixed signs with -FLT_MAX init)
    if (v >= 0.f) atomicMax((int*)a, __float_as_int(v));
    else          atomicMin((unsigned int*)a, __float_as_uint(v));
}

// ---------------- trivial kernels ----------------
__global__ void k_copy_h(const float* __restrict__ x) {
    int i = blockIdx.x * blockDim.x + threadIdx.x;
    if (i < NN * ND) g_h[i] = x[i];
}

__global__ void k_init_layer() {
    int i = blockIdx.x * blockDim.x + threadIdx.x;
    int stride = gridDim.x * blockDim.x;
    for (int j = i; j < NN * ND; j += stride) g_agg[j] = 0.f;
    for (int j = i; j < NN; j += stride) {
        g_segmax[j] = -3.402823466e38f;
        g_denom[j]  = 0.f;
    }
}

// hd = h @ Wd  (50000 x 64 @ 64 x 64)
__global__ void k_dense(const float* __restrict__ Wd) {
    __shared__ float sW[64 * 64];
    __shared__ float sh[4][64];
    int t = threadIdx.x;  // 256
    for (int i = t; i < 64 * 64; i += 256) sW[i] = Wd[i];
    __syncthreads();
    int r = t >> 6, c = t & 63;
    for (int base = blockIdx.x * 4; base < NN; base += gridDim.x * 4) {
        int n = base + r;
        if (n < NN) sh[r][c] = g_h[n * ND + c];
        __syncthreads();
        if (n < NN) {
            float acc = 0.f;
            #pragma unroll
            for (int k = 0; k < 64; k++) acc = fmaf(sh[r][k], sW[k * 64 + c], acc);
            g_hd[n * ND + c] = acc;
        }
        __syncthreads();
    }
}

// ---------------- edge MLP + message + score + segmax (warp per edge) ----------------
// dyn smem layout (floats): sW1[4096] sW2[8192] sb1[128] sb2[64] sav[64] sEa[8*32] sHid[8*128]
#define EDGE_SMEM_F (4096 + 8192 + 128 + 64 + 64 + 256 + 1024)
__global__ void k_edge_mlp(const float* __restrict__ ea,
                           const int*   __restrict__ ei,
                           const float* __restrict__ W1,
                           const float* __restrict__ b1,
                           const float* __restrict__ W2,
                           const float* __restrict__ b2,
                           const float* __restrict__ av) {
    extern __shared__ float sm[];
    float* sW1  = sm;
    float* sW2  = sm + 4096;
    float* sb1  = sm + 12288;
    float* sb2  = sm + 12416;
    float* sav  = sm + 12480;
    float* sEa  = sm + 12544;
    float* sHid = sm + 12800;
    int t = threadIdx.x;  // 256
    for (int i = t; i < 4096; i += 256) sW1[i] = W1[i];
    for (int i = t; i < 8192; i += 256) sW2[i] = W2[i];
    if (t < 128) sb1[t] = b1[t];
    if (t < 64) { sb2[t] = b2[t]; sav[t] = av[t]; }
    __syncthreads();

    int w = t >> 5, l = t & 31;
    float* eaw  = sEa + w * 32;
    float* hidw = sHid + w * 128;
    const int* src = ei;
    const int* tgt = ei + NE;
    int warpId = blockIdx.x * 8 + w;
    int nw = gridDim.x * 8;

    for (int e = warpId; e < NE; e += nw) {
        eaw[l] = ea[e * ED + l];
        __syncwarp();
        // hidden layer: lane owns cols 4l..4l+3
        float4 acc = *(const float4*)(sb1 + 4 * l);
        #pragma unroll
        for (int k = 0; k < 32; k++) {
            float a = eaw[k];
            float4 wv = *(const float4*)(sW1 + k * 128 + 4 * l);
            acc.x = fmaf(a, wv.x, acc.x);
            acc.y = fmaf(a, wv.y, acc.y);
            acc.z = fmaf(a, wv.z, acc.z);
            acc.w = fmaf(a, wv.w, acc.w);
        }
        acc.x = tanhf(acc.x); acc.y = tanhf(acc.y);
        acc.z = tanhf(acc.z); acc.w = tanhf(acc.w);
        *(float4*)(hidw + 4 * l) = acc;
        __syncwarp();
        // output layer: lane owns cols 2l, 2l+1
        float o0 = sb2[2 * l], o1 = sb2[2 * l + 1];
        #pragma unroll 8
        for (int k = 0; k < 128; k += 4) {
            float4 hv = *(const float4*)(hidw + k);
            float2 wa = *(const float2*)(sW2 + (k    ) * 64 + 2 * l);
            float2 wb = *(const float2*)(sW2 + (k + 1) * 64 + 2 * l);
            float2 wc = *(const float2*)(sW2 + (k + 2) * 64 + 2 * l);
            float2 wd = *(const float2*)(sW2 + (k + 3) * 64 + 2 * l);
            o0 = fmaf(hv.x, wa.x, o0); o1 = fmaf(hv.x, wa.y, o1);
            o0 = fmaf(hv.y, wb.x, o0); o1 = fmaf(hv.y, wb.y, o1);
            o0 = fmaf(hv.z, wc.x, o0); o1 = fmaf(hv.z, wc.y, o1);
            o0 = fmaf(hv.w, wd.x, o0); o1 = fmaf(hv.w, wd.y, o1);
        }
        int s = src[e], g = tgt[e];
        float2 hdv = *(const float2*)(g_hd + (size_t)s * ND + 2 * l);
        float m0 = hdv.x * o0, m1 = hdv.y * o1;
        *(float2*)(g_msg + (size_t)e * ND + 2 * l) = make_float2(m0, m1);
        float sc = fmaf(m0, sav[2 * l], m1 * sav[2 * l + 1]);
        #pragma unroll
        for (int off = 16; off; off >>= 1) sc += __shfl_xor_sync(0xffffffffu, sc, off);
        if (l == 0) {
            g_score[e] = sc;
            atomicMaxF(&g_segmax[g], sc);
        }
        __syncwarp();
    }
}

__global__ void k_edge_soft(const int* __restrict__ ei) {
    int e = blockIdx.x * blockDim.x + threadIdx.x;
    if (e >= NE) return;
    int g = ei[NE + e];
    float ex = expf(g_score[e] - g_segmax[g]);
    g_expw[e] = ex;
    atomicAdd(&g_denom[g], ex);
}

__global__ void k_edge_agg(const int* __restrict__ ei) {
    long gid = blockIdx.x * (long)blockDim.x + threadIdx.x;
    if (gid >= (long)NE * 16) return;
    int e = (int)(gid >> 4);
    int c = ((int)gid & 15) * 4;
    int g = ei[NE + e];
    float wgt = g_expw[e] / g_denom[g];
    float4 m = *(const float4*)(g_msg + (size_t)e * ND + c);
    m.x *= wgt; m.y *= wgt; m.z *= wgt; m.w *= wgt;
    atomicAdd((float4*)(g_agg + (size_t)g * ND + c), m);
}

// ---------------- node update MLP (warp per node) ----------------
// dyn smem (floats): sW1[8192] sW2[8192] sb1[128] sb2[64] sAgg[8*64] sHid[8*128]
#define NODE_SMEM_F (8192 + 8192 + 128 + 64 + 512 + 1024)
__global__ void k_node(const float* __restrict__ W1, const float* __restrict__ b1,
                       const float* __restrict__ W2, const float* __restrict__ b2) {
    extern __shared__ float sm[];
    float* sW1  = sm;
    float* sW2  = sm + 8192;
    float* sb1  = sm + 16384;
    float* sb2  = sm + 16512;
    float* sAgg = sm + 16576;
    float* sHid = sm + 17088;
    int t = threadIdx.x;  // 256
    for (int i = t; i < 8192; i += 256) sW1[i] = W1[i];
    for (int i = t; i < 8192; i += 256) sW2[i] = W2[i];
    if (t < 128) sb1[t] = b1[t];
    if (t < 64) sb2[t] = b2[t];
    __syncthreads();

    int w = t >> 5, l = t & 31;
    float* agw  = sAgg + w * 64;
    float* hidw = sHid + w * 128;
    int warpId = blockIdx.x * 8 + w, nw = gridDim.x * 8;
    for (int n = warpId; n < NN; n += nw) {
        *(float2*)(agw + 2 * l) = *(const float2*)(g_agg + (size_t)n * ND + 2 * l);
        __syncwarp();
        float4 acc = *(const float4*)(sb1 + 4 * l);
        #pragma unroll 8
        for (int k = 0; k < 64; k++) {
            float a = agw[k];
            float4 wv = *(const float4*)(sW1 + k * 128 + 4 * l);
            acc.x = fmaf(a, wv.x, acc.x);
            acc.y = fmaf(a, wv.y, acc.y);
            acc.z = fmaf(a, wv.z, acc.z);
            acc.w = fmaf(a, wv.w, acc.w);
        }
        acc.x = tanhf(acc.x); acc.y = tanhf(acc.y);
        acc.z = tanhf(acc.z); acc.w = tanhf(acc.w);
        *(float4*)(hidw + 4 * l) = acc;
        __syncwarp();
        float o0 = sb2[2 * l], o1 = sb2[2 * l + 1];
        #pragma unroll 8
        for (int k = 0; k < 128; k += 4) {
            float4 hv = *(const float4*)(hidw + k);
            float2 wa = *(const float2*)(sW2 + (k    ) * 64 + 2 * l);
            float2 wb = *(const float2*)(sW2 + (k + 1) * 64 + 2 * l);
            float2 wc = *(const float2*)(sW2 + (k + 2) * 64 + 2 * l);
            float2 wd = *(const float2*)(sW2 + (k + 3) * 64 + 2 * l);
            o0 = fmaf(hv.x, wa.x, o0); o1 = fmaf(hv.x, wa.y, o1);
            o0 = fmaf(hv.y, wb.x, o0); o1 = fmaf(hv.y, wb.y, o1);
            o0 = fmaf(hv.z, wc.x, o0); o1 = fmaf(hv.z, wc.y, o1);
            o0 = fmaf(hv.w, wd.x, o0); o1 = fmaf(hv.w, wd.y, o1);
        }
        float2 hv2 = *(float2*)(g_h + (size_t)n * ND + 2 * l);
        hv2.x += o0; hv2.y += o1;
        *(float2*)(g_h + (size_t)n * ND + 2 * l) = hv2;
        __syncwarp();
    }
}

// ---------------- pooling + final MLP ----------------
__global__ void k_pool_init() {
    int i = threadIdx.x + blockIdx.x * blockDim.x;
    if (i < NG * ND) g_pooled[i] = 0.f;
    if (i < NG) g_cnt[i] = 0;
}

__global__ void k_pool(const int* __restrict__ batch) {
    long gid = blockIdx.x * (long)blockDim.x + threadIdx.x;
    if (gid >= (long)NN * 16) return;
    int n = (int)(gid >> 4);
    int c = ((int)gid & 15) * 4;
    int b = batch[n];
    float4 v = *(const float4*)(g_h + (size_t)n * ND + c);
    atomicAdd((float4*)(g_pooled + b * ND + c), v);
    if (c == 0) atomicAdd(&g_cnt[b], 1);
}

// dyn smem (floats): sW1[8192] sW2[4096] sb1[128] sb2[32] sP[8*64] sHid[8*128]
#define FINAL_SMEM_F (8192 + 4096 + 128 + 32 + 512 + 1024)
__global__ void k_final(const float* __restrict__ W1, const float* __restrict__ b1,
                        const float* __restrict__ W2, const float* __restrict__ b2,
                        float* __restrict__ out) {
    extern __shared__ float sm[];
    float* sW1  = sm;
    float* sW2  = sm + 8192;
    float* sb1  = sm + 12288;
    float* sb2  = sm + 12416;
    float* sP   = sm + 12448;
    float* sHid = sm + 12960;
    int t = threadIdx.x;  // 256
    for (int i = t; i < 8192; i += 256) sW1[i] = W1[i];
    for (int i = t; i < 4096; i += 256) sW2[i] = W2[i];
    if (t < 128) sb1[t] = b1[t];
    if (t < 32) sb2[t] = b2[t];
    __syncthreads();

    int w = t >> 5, l = t & 31;
    int g = blockIdx.x * 8 + w;
    if (g >= NG) return;
    float inv = 1.f / (float)max(g_cnt[g], 1);
    float* pw   = sP + w * 64;
    float* hidw = sHid + w * 128;
    float2 pv = *(const float2*)(g_pooled + g * ND + 2 * l);
    pw[2 * l] = pv.x * inv;
    pw[2 * l + 1] = pv.y * inv;
    __syncwarp();
    float4 acc = *(const float4*)(sb1 + 4 * l);
    #pragma unroll 8
    for (int k = 0; k < 64; k++) {
        float a = pw[k];
        float4 wv = *(const float4*)(sW1 + k * 128 + 4 * l);
        acc.x = fmaf(a, wv.x, acc.x);
        acc.y = fmaf(a, wv.y, acc.y);
        acc.z = fmaf(a, wv.z, acc.z);
        acc.w = fmaf(a, wv.w, acc.w);
    }
    acc.x = tanhf(acc.x); acc.y = tanhf(acc.y);
    acc.z = tanhf(acc.z); acc.w = tanhf(acc.w);
    *(float4*)(hidw + 4 * l) = acc;
    __syncwarp();
    float o = sb2[l];
    #pragma unroll 8
    for (int k = 0; k < 128; k += 4) {
        float4 hv = *(const float4*)(hidw + k);
        o = fmaf(hv.x, sW2[(k    ) * 32 + l], o);
        o = fmaf(hv.y, sW2[(k + 1) * 32 + l], o);
        o = fmaf(hv.z, sW2[(k + 2) * 32 + l], o);
        o = fmaf(hv.w, sW2[(k + 3) * 32 + l], o);
    }
    out[g * OD + l] = o;
}

// ---------------- launch ----------------
extern "C" void kernel_launch(void* const* d_in, const int* in_sizes, int n_in,
                              void* d_out, int out_size) {
    const float *x, *ea, *Wd, *fW1, *fb1, *fW2, *fb2, *av;
    const float *oW1, *ob1, *oW2, *ob2, *nW1, *nb1, *nW2, *nb2;
    const int *ei, *batch;

    if (in_sizes[2] == 2 * NE) {
        // setup_inputs dict order
        x   = (const float*)d_in[0];  ea  = (const float*)d_in[1];
        ei  = (const int*)  d_in[2];  batch = (const int*)d_in[3];
        Wd  = (const float*)d_in[4];
        fW1 = (const float*)d_in[5];  fb1 = (const float*)d_in[6];
        fW2 = (const float*)d_in[7];  fb2 = (const float*)d_in[8];
        av  = (const float*)d_in[9];
        oW1 = (const float*)d_in[10]; ob1 = (const float*)d_in[11];
        oW2 = (const float*)d_in[12]; ob2 = (const float*)d_in[13];
        nW1 = (const float*)d_in[14]; nb1 = (const float*)d_in[15];
        nW2 = (const float*)d_in[16]; nb2 = (const float*)d_in[17];
    } else {
        // reference() signature order
        x   = (const float*)d_in[0];  ea  = (const float*)d_in[1];
        Wd  = (const float*)d_in[2];
        fW1 = (const float*)d_in[3];  fb1 = (const float*)d_in[4];
        fW2 = (const float*)d_in[5];  fb2 = (const float*)d_in[6];
        av  = (const float*)d_in[7];
        oW1 = (const float*)d_in[8];  ob1 = (const float*)d_in[9];
        oW2 = (const float*)d_in[10]; ob2 = (const float*)d_in[11];
        nW1 = (const float*)d_in[12]; nb1 = (const float*)d_in[13];
        nW2 = (const float*)d_in[14]; nb2 = (const float*)d_in[15];
        ei  = (const int*)d_in[16];   batch = (const int*)d_in[17];
    }

    cudaFuncSetAttribute(k_edge_mlp, cudaFuncAttributeMaxDynamicSharedMemorySize,
                         EDGE_SMEM_F * 4);
    cudaFuncSetAttribute(k_node, cudaFuncAttributeMaxDynamicSharedMemorySize,
                         NODE_SMEM_F * 4);
    cudaFuncSetAttribute(k_final, cudaFuncAttributeMaxDynamicSharedMemorySize,
                         FINAL_SMEM_F * 4);

    k_copy_h<<<(NN * ND + 255) / 256, 256>>>(x);

    for (int i = 0; i < NL; i++) {
        k_dense<<<1480, 256>>>(Wd + i * ND * ND);
        k_init_layer<<<1480, 256>>>();
        k_edge_mlp<<<592, 256, EDGE_SMEM_F * 4>>>(
            ea, ei,
            fW1 + i * ED * NH, fb1 + i * NH,
            fW2 + i * NH * ND, fb2 + i * ND,
            av + i * ND);
        k_edge_soft<<<(NE + 255) / 256, 256>>>(ei);
        k_edge_agg<<<(int)(((long)NE * 16 + 255) / 256), 256>>>(ei);
        k_node<<<444, 256, NODE_SMEM_F * 4>>>(
            oW1 + i * ND * NH, ob1 + i * NH,
            oW2 + i * NH * ND, ob2 + i * ND);
    }

    k_pool_init<<<(NG * ND + 255) / 256, 256>>>();
    k_pool<<<(int)(((long)NN * 16 + 255) / 256), 256>>>(batch);
    k_final<<<16, 256, FINAL_SMEM_F * 4>>>(nW1, nb1, nW2, nb2, (float*)d_out);
}

// round 2
// speedup vs baseline: 1.9540x; 1.9540x over previous
#include <cuda_runtime.h>
#include <math.h>

#define NN 50000
#define NE 800000
#define ND 64
#define ED 32
#define NH 128
#define OD 32
#define NL 3
#define NG 128

// ---------------- device scratch ----------------
__device__ float g_h[NN * ND];
__device__ float g_hd[NN * ND];
__device__ float g_msg[(size_t)NE * ND];
__device__ float g_score[NE];
__device__ float g_expw[NE];
__device__ float g_segmax[NN];
__device__ float g_denom[NN];
__device__ float g_agg[NN * ND];
__device__ float g_pooled[NG * ND];
__device__ int   g_cnt[NG];

__device__ __forceinline__ void atomicMaxF(float* a, float v) {
    if (v >= 0.f) atomicMax((int*)a, __float_as_int(v));
    else          atomicMin((unsigned int*)a, __float_as_uint(v));
}

// ---------------- trivial kernels ----------------
__global__ void k_copy_h(const float* __restrict__ x) {
    int i = blockIdx.x * blockDim.x + threadIdx.x;
    if (i < NN * ND) g_h[i] = x[i];
}

__global__ void k_init_layer() {
    int i = blockIdx.x * blockDim.x + threadIdx.x;
    int stride = gridDim.x * blockDim.x;
    for (int j = i; j < NN * ND; j += stride) g_agg[j] = 0.f;
    for (int j = i; j < NN; j += stride) {
        g_segmax[j] = -3.402823466e38f;
        g_denom[j]  = 0.f;
    }
}

// hd = h @ Wd  (50000 x 64 @ 64 x 64)
__global__ void k_dense(const float* __restrict__ Wd) {
    __shared__ float sW[64 * 64];
    __shared__ float sh[4][64];
    int t = threadIdx.x;  // 256
    for (int i = t; i < 64 * 64; i += 256) sW[i] = Wd[i];
    __syncthreads();
    int r = t >> 6, c = t & 63;
    for (int base = blockIdx.x * 4; base < NN; base += gridDim.x * 4) {
        int n = base + r;
        if (n < NN) sh[r][c] = g_h[n * ND + c];
        __syncthreads();
        if (n < NN) {
            float acc = 0.f;
            #pragma unroll
            for (int k = 0; k < 64; k++) acc = fmaf(sh[r][k], sW[k * 64 + c], acc);
            g_hd[n * ND + c] = acc;
        }
        __syncthreads();
    }
}

// ============ edge MLP: 4 edges per warp iteration, transposed activations ============
// smem floats: sW1[4096] sW2[8192] sb1[128] sb2[64] sav[64] | per-warp sEaT[32*4]*8 sHidT[128*4]*8
#define EDGE_SMEM_F (4096 + 8192 + 128 + 64 + 64 + 8 * 128 + 8 * 512)
__global__ void __launch_bounds__(256) k_edge_mlp(
        const float* __restrict__ ea,
        const int*   __restrict__ ei,
        const float* __restrict__ W1,
        const float* __restrict__ b1,
        const float* __restrict__ W2,
        const float* __restrict__ b2,
        const float* __restrict__ av) {
    extern __shared__ float sm[];
    float* sW1  = sm;                 // 4096
    float* sW2  = sm + 4096;          // 8192
    float* sb1  = sm + 12288;         // 128
    float* sb2  = sm + 12416;         // 64
    float* sav  = sm + 12480;         // 64
    float* sEaT = sm + 12544;         // 8 * 128
    float* sHidT= sm + 12544 + 1024;  // 8 * 512
    int t = threadIdx.x;
    for (int i = t; i < 4096; i += 256) sW1[i] = W1[i];
    for (int i = t; i < 8192; i += 256) sW2[i] = W2[i];
    if (t < 128) sb1[t] = b1[t];
    if (t < 64) { sb2[t] = b2[t]; sav[t] = av[t]; }
    __syncthreads();

    int w = t >> 5, l = t & 31;
    float* eaT  = sEaT  + w * 128;   // [k 0..31][edge 0..3]
    float* hidT = sHidT + w * 512;   // [k 0..127][edge 0..3]
    const int* src = ei;
    const int* tgt = ei + NE;
    const int NGRP = NE / 4;         // 200000
    int grp = blockIdx.x * 8 + w;
    int ngrp = gridDim.x * 8;
    float av0 = 0.f, av1 = 0.f;      // cache attn_v for this lane
    av0 = sav[2 * l]; av1 = sav[2 * l + 1];

    for (int gi = grp; gi < NGRP; gi += ngrp) {
        int e0 = gi * 4;
        // load edge_attr transposed: eaT[k*4 + i]
        #pragma unroll
        for (int i = 0; i < 4; i++)
            eaT[l * 4 + i] = ea[(size_t)(e0 + i) * ED + l];
        __syncwarp();

        // ---- hidden layer: lane owns cols 4l..4l+3, vector dim = edges ----
        float b;
        b = sb1[4 * l + 0]; float4 a0 = make_float4(b, b, b, b);
        b = sb1[4 * l + 1]; float4 a1 = make_float4(b, b, b, b);
        b = sb1[4 * l + 2]; float4 a2 = make_float4(b, b, b, b);
        b = sb1[4 * l + 3]; float4 a3 = make_float4(b, b, b, b);
        #pragma unroll
        for (int k = 0; k < 32; k++) {
            float4 e4 = *(const float4*)(eaT + k * 4);         // broadcast
            float4 w4 = *(const float4*)(sW1 + k * 128 + 4 * l);
            a0.x = fmaf(e4.x, w4.x, a0.x); a0.y = fmaf(e4.y, w4.x, a0.y);
            a0.z = fmaf(e4.z, w4.x, a0.z); a0.w = fmaf(e4.w, w4.x, a0.w);
            a1.x = fmaf(e4.x, w4.y, a1.x); a1.y = fmaf(e4.y, w4.y, a1.y);
            a1.z = fmaf(e4.z, w4.y, a1.z); a1.w = fmaf(e4.w, w4.y, a1.w);
            a2.x = fmaf(e4.x, w4.z, a2.x); a2.y = fmaf(e4.y, w4.z, a2.y);
            a2.z = fmaf(e4.z, w4.z, a2.z); a2.w = fmaf(e4.w, w4.z, a2.w);
            a3.x = fmaf(e4.x, w4.w, a3.x); a3.y = fmaf(e4.y, w4.w, a3.y);
            a3.z = fmaf(e4.z, w4.w, a3.z); a3.w = fmaf(e4.w, w4.w, a3.w);
        }
        a0.x = tanhf(a0.x); a0.y = tanhf(a0.y); a0.z = tanhf(a0.z); a0.w = tanhf(a0.w);
        a1.x = tanhf(a1.x); a1.y = tanhf(a1.y); a1.z = tanhf(a1.z); a1.w = tanhf(a1.w);
        a2.x = tanhf(a2.x); a2.y = tanhf(a2.y); a2.z = tanhf(a2.z); a2.w = tanhf(a2.w);
        a3.x = tanhf(a3.x); a3.y = tanhf(a3.y); a3.z = tanhf(a3.z); a3.w = tanhf(a3.w);
        *(float4*)(hidT + (4 * l + 0) * 4) = a0;
        *(float4*)(hidT + (4 * l + 1) * 4) = a1;
        *(float4*)(hidT + (4 * l + 2) * 4) = a2;
        *(float4*)(hidT + (4 * l + 3) * 4) = a3;
        __syncwarp();

        // ---- output layer: lane owns cols 2l, 2l+1 ----
        b = sb2[2 * l];     float4 o0 = make_float4(b, b, b, b);
        b = sb2[2 * l + 1]; float4 o1 = make_float4(b, b, b, b);
        #pragma unroll 8
        for (int k = 0; k < 128; k++) {
            float4 h4 = *(const float4*)(hidT + k * 4);        // broadcast
            float2 w2 = *(const float2*)(sW2 + k * 64 + 2 * l);
            o0.x = fmaf(h4.x, w2.x, o0.x); o0.y = fmaf(h4.y, w2.x, o0.y);
            o0.z = fmaf(h4.z, w2.x, o0.z); o0.w = fmaf(h4.w, w2.x, o0.w);
            o1.x = fmaf(h4.x, w2.y, o1.x); o1.y = fmaf(h4.y, w2.y, o1.y);
            o1.z = fmaf(h4.z, w2.y, o1.z); o1.w = fmaf(h4.w, w2.y, o1.w);
        }

        // ---- epilogue: gather hd, messages, score, segmax ----
        #define EDGE_EPI(I, O0, O1) {                                              \
            int s_ = src[e0 + I], g_ = tgt[e0 + I];                                \
            float2 hd_ = *(const float2*)(g_hd + (size_t)s_ * ND + 2 * l);         \
            float m0_ = hd_.x * (O0), m1_ = hd_.y * (O1);                          \
            *(float2*)(g_msg + (size_t)(e0 + I) * ND + 2 * l) =                    \
                make_float2(m0_, m1_);                                             \
            float sc_ = fmaf(m0_, av0, m1_ * av1);                                 \
            for (int off_ = 16; off_; off_ >>= 1)                                  \
                sc_ += __shfl_xor_sync(0xffffffffu, sc_, off_);                    \
            if (l == 0) { g_score[e0 + I] = sc_; atomicMaxF(&g_segmax[g_], sc_); } \
        }
        EDGE_EPI(0, o0.x, o1.x)
        EDGE_EPI(1, o0.y, o1.y)
        EDGE_EPI(2, o0.z, o1.z)
        EDGE_EPI(3, o0.w, o1.w)
        #undef EDGE_EPI
        __syncwarp();
    }
}

__global__ void k_edge_soft(const int* __restrict__ ei) {
    int e = blockIdx.x * blockDim.x + threadIdx.x;
    if (e >= NE) return;
    int g = ei[NE + e];
    float ex = expf(g_score[e] - g_segmax[g]);
    g_expw[e] = ex;
    atomicAdd(&g_denom[g], ex);
}

__global__ void k_edge_agg(const int* __restrict__ ei) {
    long gid = blockIdx.x * (long)blockDim.x + threadIdx.x;
    if (gid >= (long)NE * 16) return;
    int e = (int)(gid >> 4);
    int c = ((int)gid & 15) * 4;
    int g = ei[NE + e];
    float wgt = g_expw[e] / g_denom[g];
    float4 m = *(const float4*)(g_msg + (size_t)e * ND + c);
    m.x *= wgt; m.y *= wgt; m.z *= wgt; m.w *= wgt;
    atomicAdd((float4*)(g_agg + (size_t)g * ND + c), m);
}

// ============ node update MLP: 4 nodes per warp iteration ============
// smem floats: sW1[8192] sW2[8192] sb1[128] sb2[64] | per-warp sAggT[64*4]*8 sHidT[128*4]*8
#define NODE_SMEM_F (8192 + 8192 + 128 + 64 + 8 * 256 + 8 * 512)
__global__ void __launch_bounds__(256) k_node(
        const float* __restrict__ W1, const float* __restrict__ b1,
        const float* __restrict__ W2, const float* __restrict__ b2) {
    extern __shared__ float sm[];
    float* sW1   = sm;                 // 8192
    float* sW2   = sm + 8192;          // 8192
    float* sb1   = sm + 16384;         // 128
    float* sb2   = sm + 16512;         // 64
    float* sAggT = sm + 16576;         // 8 * 256
    float* sHidT = sm + 16576 + 2048;  // 8 * 512
    int t = threadIdx.x;
    for (int i = t; i < 8192; i += 256) sW1[i] = W1[i];
    for (int i = t; i < 8192; i += 256) sW2[i] = W2[i];
    if (t < 128) sb1[t] = b1[t];
    if (t < 64) sb2[t] = b2[t];
    __syncthreads();

    int w = t >> 5, l = t & 31;
    float* agT  = sAggT + w * 256;   // [k 0..63][node 0..3]
    float* hidT = sHidT + w * 512;
    const int NGRP = NN / 4;         // 12500
    int grp = blockIdx.x * 8 + w;
    int ngrp = gridDim.x * 8;

    for (int gi = grp; gi < NGRP; gi += ngrp) {
        int n0 = gi * 4;
        #pragma unroll
        for (int i = 0; i < 4; i++) {
            float2 v = *(const float2*)(g_agg + (size_t)(n0 + i) * ND + 2 * l);
            agT[(2 * l) * 4 + i]     = v.x;
            agT[(2 * l + 1) * 4 + i] = v.y;
        }
        __syncwarp();

        float b;
        b = sb1[4 * l + 0]; float4 a0 = make_float4(b, b, b, b);
        b = sb1[4 * l + 1]; float4 a1 = make_float4(b, b, b, b);
        b = sb1[4 * l + 2]; float4 a2 = make_float4(b, b, b, b);
        b = sb1[4 * l + 3]; float4 a3 = make_float4(b, b, b, b);
        #pragma unroll 8
        for (int k = 0; k < 64; k++) {
            float4 e4 = *(const float4*)(agT + k * 4);
            float4 w4 = *(const float4*)(sW1 + k * 128 + 4 * l);
            a0.x = fmaf(e4.x, w4.x, a0.x); a0.y = fmaf(e4.y, w4.x, a0.y);
            a0.z = fmaf(e4.z, w4.x, a0.z); a0.w = fmaf(e4.w, w4.x, a0.w);
            a1.x = fmaf(e4.x, w4.y, a1.x); a1.y = fmaf(e4.y, w4.y, a1.y);
            a1.z = fmaf(e4.z, w4.y, a1.z); a1.w = fmaf(e4.w, w4.y, a1.w);
            a2.x = fmaf(e4.x, w4.z, a2.x); a2.y = fmaf(e4.y, w4.z, a2.y);
            a2.z = fmaf(e4.z, w4.z, a2.z); a2.w = fmaf(e4.w, w4.z, a2.w);
            a3.x = fmaf(e4.x, w4.w, a3.x); a3.y = fmaf(e4.y, w4.w, a3.y);
            a3.z = fmaf(e4.z, w4.w, a3.z); a3.w = fmaf(e4.w, w4.w, a3.w);
        }
        a0.x = tanhf(a0.x); a0.y = tanhf(a0.y); a0.z = tanhf(a0.z); a0.w = tanhf(a0.w);
        a1.x = tanhf(a1.x); a1.y = tanhf(a1.y); a1.z = tanhf(a1.z); a1.w = tanhf(a1.w);
        a2.x = tanhf(a2.x); a2.y = tanhf(a2.y); a2.z = tanhf(a2.z); a2.w = tanhf(a2.w);
        a3.x = tanhf(a3.x); a3.y = tanhf(a3.y); a3.z = tanhf(a3.z); a3.w = tanhf(a3.w);
        *(float4*)(hidT + (4 * l + 0) * 4) = a0;
        *(float4*)(hidT + (4 * l + 1) * 4) = a1;
        *(float4*)(hidT + (4 * l + 2) * 4) = a2;
        *(float4*)(hidT + (4 * l + 3) * 4) = a3;
        __syncwarp();

        b = sb2[2 * l];     float4 o0 = make_float4(b, b, b, b);
        b = sb2[2 * l + 1]; float4 o1 = make_float4(b, b, b, b);
        #pragma unroll 8
        for (int k = 0; k < 128; k++) {
            float4 h4 = *(const float4*)(hidT + k * 4);
            float2 w2 = *(const float2*)(sW2 + k * 64 + 2 * l);
            o0.x = fmaf(h4.x, w2.x, o0.x); o0.y = fmaf(h4.y, w2.x, o0.y);
            o0.z = fmaf(h4.z, w2.x, o0.z); o0.w = fmaf(h4.w, w2.x, o0.w);
            o1.x = fmaf(h4.x, w2.y, o1.x); o1.y = fmaf(h4.y, w2.y, o1.y);
            o1.z = fmaf(h4.z, w2.y, o1.z); o1.w = fmaf(h4.w, w2.y, o1.w);
        }

        #define NODE_EPI(I, O0, O1) {                                        \
            float2 hv_ = *(float2*)(g_h + (size_t)(n0 + I) * ND + 2 * l);    \
            hv_.x += (O0); hv_.y += (O1);                                    \
            *(float2*)(g_h + (size_t)(n0 + I) * ND + 2 * l) = hv_;           \
        }
        NODE_EPI(0, o0.x, o1.x)
        NODE_EPI(1, o0.y, o1.y)
        NODE_EPI(2, o0.z, o1.z)
        NODE_EPI(3, o0.w, o1.w)
        #undef NODE_EPI
        __syncwarp();
    }
}

// ---------------- pooling + final MLP ----------------
__global__ void k_pool_init() {
    int i = threadIdx.x + blockIdx.x * blockDim.x;
    if (i < NG * ND) g_pooled[i] = 0.f;
    if (i < NG) g_cnt[i] = 0;
}

__global__ void k_pool(const int* __restrict__ batch) {
    long gid = blockIdx.x * (long)blockDim.x + threadIdx.x;
    if (gid >= (long)NN * 16) return;
    int n = (int)(gid >> 4);
    int c = ((int)gid & 15) * 4;
    int b = batch[n];
    float4 v = *(const float4*)(g_h + (size_t)n * ND + c);
    atomicAdd((float4*)(g_pooled + b * ND + c), v);
    if (c == 0) atomicAdd(&g_cnt[b], 1);
}

#define FINAL_SMEM_F (8192 + 4096 + 128 + 32 + 512 + 1024)
__global__ void k_final(const float* __restrict__ W1, const float* __restrict__ b1,
                        const float* __restrict__ W2, const float* __restrict__ b2,
                        float* __restrict__ out) {
    extern __shared__ float sm[];
    float* sW1  = sm;
    float* sW2  = sm + 8192;
    float* sb1  = sm + 12288;
    float* sb2  = sm + 12416;
    float* sP   = sm + 12448;
    float* sHid = sm + 12960;
    int t = threadIdx.x;  // 256
    for (int i = t; i < 8192; i += 256) sW1[i] = W1[i];
    for (int i = t; i < 4096; i += 256) sW2[i] = W2[i];
    if (t < 128) sb1[t] = b1[t];
    if (t < 32) sb2[t] = b2[t];
    __syncthreads();

    int w = t >> 5, l = t & 31;
    int g = blockIdx.x * 8 + w;
    if (g >= NG) return;
    float inv = 1.f / (float)max(g_cnt[g], 1);
    float* pw   = sP + w * 64;
    float* hidw = sHid + w * 128;
    float2 pv = *(const float2*)(g_pooled + g * ND + 2 * l);
    pw[2 * l] = pv.x * inv;
    pw[2 * l + 1] = pv.y * inv;
    __syncwarp();
    float4 acc = *(const float4*)(sb1 + 4 * l);
    #pragma unroll 8
    for (int k = 0; k < 64; k++) {
        float a = pw[k];
        float4 wv = *(const float4*)(sW1 + k * 128 + 4 * l);
        acc.x = fmaf(a, wv.x, acc.x);
        acc.y = fmaf(a, wv.y, acc.y);
        acc.z = fmaf(a, wv.z, acc.z);
        acc.w = fmaf(a, wv.w, acc.w);
    }
    acc.x = tanhf(acc.x); acc.y = tanhf(acc.y);
    acc.z = tanhf(acc.z); acc.w = tanhf(acc.w);
    *(float4*)(hidw + 4 * l) = acc;
    __syncwarp();
    float o = sb2[l];
    #pragma unroll 8
    for (int k = 0; k < 128; k += 4) {
        float4 hv = *(const float4*)(hidw + k);
        o = fmaf(hv.x, sW2[(k    ) * 32 + l], o);
        o = fmaf(hv.y, sW2[(k + 1) * 32 + l], o);
        o = fmaf(hv.z, sW2[(k + 2) * 32 + l], o);
        o = fmaf(hv.w, sW2[(k + 3) * 32 + l], o);
    }
    out[g * OD + l] = o;
}

// ---------------- launch ----------------
extern "C" void kernel_launch(void* const* d_in, const int* in_sizes, int n_in,
                              void* d_out, int out_size) {
    const float *x, *ea, *Wd, *fW1, *fb1, *fW2, *fb2, *av;
    const float *oW1, *ob1, *oW2, *ob2, *nW1, *nb1, *nW2, *nb2;
    const int *ei, *batch;

    if (in_sizes[2] == 2 * NE) {
        x   = (const float*)d_in[0];  ea  = (const float*)d_in[1];
        ei  = (const int*)  d_in[2];  batch = (const int*)d_in[3];
        Wd  = (const float*)d_in[4];
        fW1 = (const float*)d_in[5];  fb1 = (const float*)d_in[6];
        fW2 = (const float*)d_in[7];  fb2 = (const float*)d_in[8];
        av  = (const float*)d_in[9];
        oW1 = (const float*)d_in[10]; ob1 = (const float*)d_in[11];
        oW2 = (const float*)d_in[12]; ob2 = (const float*)d_in[13];
        nW1 = (const float*)d_in[14]; nb1 = (const float*)d_in[15];
        nW2 = (const float*)d_in[16]; nb2 = (const float*)d_in[17];
    } else {
        x   = (const float*)d_in[0];  ea  = (const float*)d_in[1];
        Wd  = (const float*)d_in[2];
        fW1 = (const float*)d_in[3];  fb1 = (const float*)d_in[4];
        fW2 = (const float*)d_in[5];  fb2 = (const float*)d_in[6];
        av  = (const float*)d_in[7];
        oW1 = (const float*)d_in[8];  ob1 = (const float*)d_in[9];
        oW2 = (const float*)d_in[10]; ob2 = (const float*)d_in[11];
        nW1 = (const float*)d_in[12]; nb1 = (const float*)d_in[13];
        nW2 = (const float*)d_in[14]; nb2 = (const float*)d_in[15];
        ei  = (const int*)d_in[16];   batch = (const int*)d_in[17];
    }

    cudaFuncSetAttribute(k_edge_mlp, cudaFuncAttributeMaxDynamicSharedMemorySize,
                         EDGE_SMEM_F * 4);
    cudaFuncSetAttribute(k_node, cudaFuncAttributeMaxDynamicSharedMemorySize,
                         NODE_SMEM_F * 4);
    cudaFuncSetAttribute(k_final, cudaFuncAttributeMaxDynamicSharedMemorySize,
                         FINAL_SMEM_F * 4);

    k_copy_h<<<(NN * ND + 255) / 256, 256>>>(x);

    for (int i = 0; i < NL; i++) {
        k_dense<<<1480, 256>>>(Wd + i * ND * ND);
        k_init_layer<<<1480, 256>>>();
        k_edge_mlp<<<444, 256, EDGE_SMEM_F * 4>>>(
            ea, ei,
            fW1 + i * ED * NH, fb1 + i * NH,
            fW2 + i * NH * ND, fb2 + i * ND,
            av + i * ND);
        k_edge_soft<<<(NE + 255) / 256, 256>>>(ei);
        k_edge_agg<<<(int)(((long)NE * 16 + 255) / 256), 256>>>(ei);
        k_node<<<296, 256, NODE_SMEM_F * 4>>>(
            oW1 + i * ND * NH, ob1 + i * NH,
            oW2 + i * NH * ND, ob2 + i * ND);
    }

    k_pool_init<<<(NG * ND + 255) / 256, 256>>>();
    k_pool<<<(int)(((long)NN * 16 + 255) / 256), 256>>>(batch);
    k_final<<<16, 256, FINAL_SMEM_F * 4>>>(nW1, nb1, nW2, nb2, (float*)d_out);
}

// round 4
// speedup vs baseline: 3.1891x; 1.6321x over previous
#include <cuda_runtime.h>
#include <math.h>
#include <stdint.h>

#define NN 50000
#define NE 800000
#define ND 64
#define ED 32
#define NH 128
#define OD 32
#define NL 3
#define NG 128
#define ETILE 64
#define NTILES (NE / ETILE)   // 12500

// ---------------- device scratch ----------------
__device__ float g_h[NN * ND];
__device__ float g_hd[NN * ND];
__device__ float g_msg[(size_t)NE * ND];
__device__ float g_score[NE];
__device__ float g_segmax[NN];
__device__ float g_denom[NN];
__device__ float g_agg[NN * ND];
__device__ float g_pooled[NG * ND];
__device__ int   g_cnt[NG];

__device__ __forceinline__ void atomicMaxF(float* a, float v) {
    if (v >= 0.f) atomicMax((int*)a, __float_as_int(v));
    else          atomicMin((unsigned int*)a, __float_as_uint(v));
}

__device__ __forceinline__ uint32_t f2tf(float f) {
    uint32_t r;
    asm("cvt.rna.tf32.f32 %0, %1;" : "=r"(r) : "f"(f));
    return r;
}

__device__ __forceinline__ void mma_tf32(float* c, const uint32_t* a, const uint32_t* b) {
    asm volatile(
        "mma.sync.aligned.m16n8k8.row.col.f32.tf32.tf32.f32 "
        "{%0,%1,%2,%3}, {%4,%5,%6,%7}, {%8,%9}, {%0,%1,%2,%3};"
        : "+f"(c[0]), "+f"(c[1]), "+f"(c[2]), "+f"(c[3])
        : "r"(a[0]), "r"(a[1]), "r"(a[2]), "r"(a[3]), "r"(b[0]), "r"(b[1]));
}

// ---------------- trivial kernels ----------------
__global__ void k_copy_h(const float* __restrict__ x) {
    int i = blockIdx.x * blockDim.x + threadIdx.x;
    if (i < NN * ND) g_h[i] = x[i];
}

__global__ void k_init_layer() {
    int i = blockIdx.x * blockDim.x + threadIdx.x;
    int stride = gridDim.x * blockDim.x;
    for (int j = i; j < NN * ND; j += stride) g_agg[j] = 0.f;
    for (int j = i; j < NN; j += stride) {
        g_segmax[j] = -3.402823466e38f;
        g_denom[j]  = 0.f;
    }
}

// hd = h @ Wd
__global__ void k_dense(const float* __restrict__ Wd) {
    __shared__ float sW[64 * 64];
    __shared__ float sh[4][64];
    int t = threadIdx.x;
    for (int i = t; i < 64 * 64; i += 256) sW[i] = Wd[i];
    __syncthreads();
    int r = t >> 6, c = t & 63;
    for (int base = blockIdx.x * 4; base < NN; base += gridDim.x * 4) {
        int n = base + r;
        if (n < NN) sh[r][c] = g_h[n * ND + c];
        __syncthreads();
        if (n < NN) {
            float acc = 0.f;
            #pragma unroll
            for (int k = 0; k < 64; k++) acc = fmaf(sh[r][k], sW[k * 64 + c], acc);
            g_hd[n * ND + c] = acc;
        }
        __syncthreads();
    }
}

// ============ edge MLP via warp-level tf32 MMA ============
// smem floats: sA[64*36]=2304 @0 | sHid[64*132]=8448 @2304 | sB1[4096] @10752 |
//              sB2[8192] @14848 | sBias[256] @23040  -> total 23296 f = 93184 B
#define O_A 0
#define O_HID 2304
#define O_B1 10752
#define O_B2 14848
#define O_BIAS 23040
#define EDGE_SMEM_F 23296

__global__ void __launch_bounds__(256) k_edge_mma(
        const float* __restrict__ ea, const int* __restrict__ ei,
        const float* __restrict__ W1, const float* __restrict__ b1,
        const float* __restrict__ W2, const float* __restrict__ b2,
        const float* __restrict__ av) {
    extern __shared__ float sm[];
    float* sA   = sm + O_A;     // [64][36] tf32 bits
    float* sHid = sm + O_HID;   // [64][132]
    float* sB1  = sm + O_B1;    // frag-packed W1
    float* sB2  = sm + O_B2;    // frag-packed W2
    float* sBias= sm + O_BIAS;  // b1[128] b2[64] av[64]
    int tid = threadIdx.x;
    int lane = tid & 31, wid = tid >> 5;
    int g = lane >> 2, tg = lane & 3;   // groupID, threadID_in_group

    // ---- pack W1 fragments: sB1[(ks*16+nt)*64 + lane*2 + j] ----
    // b0 = W1[ks*8+tg][nt*8+g], b1 = W1[ks*8+tg+4][nt*8+g]
    for (int idx = tid; idx < 4 * 16 * 32; idx += 256) {
        int l = idx & 31, nt = (idx >> 5) & 15, ks = idx >> 9;
        int kk = ks * 8 + (l & 3), nn = nt * 8 + (l >> 2);
        float2 v;
        v.x = __uint_as_float(f2tf(W1[kk * NH + nn]));
        v.y = __uint_as_float(f2tf(W1[(kk + 4) * NH + nn]));
        *(float2*)(sB1 + (size_t)idx * 2) = v;
    }
    // ---- pack W2 fragments: sB2[(ks*8+nt)*64 + lane*2 + j] ----
    for (int idx = tid; idx < 16 * 8 * 32; idx += 256) {
        int l = idx & 31, nt = (idx >> 5) & 7, ks = idx >> 8;
        int kk = ks * 8 + (l & 3), nn = nt * 8 + (l >> 2);
        float2 v;
        v.x = __uint_as_float(f2tf(W2[kk * ND + nn]));
        v.y = __uint_as_float(f2tf(W2[(kk + 4) * ND + nn]));
        *(float2*)(sB2 + (size_t)idx * 2) = v;
    }
    if (tid < 128) sBias[tid] = b1[tid];
    if (tid < 64)  sBias[128 + tid] = b2[tid];
    if (tid < 64)  sBias[192 + tid] = av[tid];
    __syncthreads();

    const int* src = ei;
    const int* tgt = ei + NE;
    int mt = wid & 3;        // m-tile (16 edges)
    int nh = wid >> 2;       // n-half

    for (int tile = blockIdx.x; tile < NTILES; tile += gridDim.x) {
        // ---- load A tile (64 edges x 32), tf32-rounded, stride 36 ----
        {
            int e_l = tid >> 2, q = tid & 3;
            const float4* rp = (const float4*)(ea + (size_t)(tile * ETILE + e_l) * ED + q * 8);
            float4 v0 = rp[0], v1 = rp[1];
            v0.x = __uint_as_float(f2tf(v0.x)); v0.y = __uint_as_float(f2tf(v0.y));
            v0.z = __uint_as_float(f2tf(v0.z)); v0.w = __uint_as_float(f2tf(v0.w));
            v1.x = __uint_as_float(f2tf(v1.x)); v1.y = __uint_as_float(f2tf(v1.y));
            v1.z = __uint_as_float(f2tf(v1.z)); v1.w = __uint_as_float(f2tf(v1.w));
            *(float4*)(sA + e_l * 36 + q * 8)     = v0;
            *(float4*)(sA + e_l * 36 + q * 8 + 4) = v1;
        }
        __syncthreads();

        // ---- GEMM1: hid[64x128] = A @ W1 ----
        float C1[8][4];
        #pragma unroll
        for (int nt = 0; nt < 8; nt++)
            C1[nt][0] = C1[nt][1] = C1[nt][2] = C1[nt][3] = 0.f;
        #pragma unroll
        for (int ks = 0; ks < 4; ks++) {
            uint32_t a[4];
            int r0 = (mt * 16 + g) * 36 + ks * 8 + tg;
            a[0] = __float_as_uint(sA[r0]);
            a[1] = __float_as_uint(sA[r0 + 8 * 36]);
            a[2] = __float_as_uint(sA[r0 + 4]);
            a[3] = __float_as_uint(sA[r0 + 8 * 36 + 4]);
            #pragma unroll
            for (int nt = 0; nt < 8; nt++) {
                int ntg = nh * 8 + nt;
                float2 bf = *(const float2*)(sB1 + (ks * 16 + ntg) * 64 + 2 * lane);
                uint32_t b[2] = { __float_as_uint(bf.x), __float_as_uint(bf.y) };
                mma_tf32(C1[nt], a, b);
            }
        }
        // ---- bias + tanh -> sHid (tf32-rounded), stride 132 ----
        #pragma unroll
        for (int nt = 0; nt < 8; nt++) {
            int col = (nh * 8 + nt) * 8 + 2 * tg;
            float bb0 = sBias[col], bb1 = sBias[col + 1];
            float2 lo, hi;
            lo.x = __uint_as_float(f2tf(tanhf(C1[nt][0] + bb0)));
            lo.y = __uint_as_float(f2tf(tanhf(C1[nt][1] + bb1)));
            hi.x = __uint_as_float(f2tf(tanhf(C1[nt][2] + bb0)));
            hi.y = __uint_as_float(f2tf(tanhf(C1[nt][3] + bb1)));
            *(float2*)(sHid + (mt * 16 + g) * 132 + col)     = lo;
            *(float2*)(sHid + (mt * 16 + g + 8) * 132 + col) = hi;
        }
        __syncthreads();

        // ---- GEMM2: ew[64x64] = hid @ W2 ----
        float C2[4][4];
        #pragma unroll
        for (int nt = 0; nt < 4; nt++)
            C2[nt][0] = C2[nt][1] = C2[nt][2] = C2[nt][3] = 0.f;
        #pragma unroll
        for (int ks = 0; ks < 16; ks++) {
            uint32_t a[4];
            int r0 = (mt * 16 + g) * 132 + ks * 8 + tg;
            a[0] = __float_as_uint(sHid[r0]);
            a[1] = __float_as_uint(sHid[r0 + 8 * 132]);
            a[2] = __float_as_uint(sHid[r0 + 4]);
            a[3] = __float_as_uint(sHid[r0 + 8 * 132 + 4]);
            #pragma unroll
            for (int nt = 0; nt < 4; nt++) {
                int ntg = nh * 4 + nt;
                float2 bf = *(const float2*)(sB2 + (ks * 8 + ntg) * 64 + 2 * lane);
                uint32_t b[2] = { __float_as_uint(bf.x), __float_as_uint(bf.y) };
                mma_tf32(C2[nt], a, b);
            }
        }
        __syncthreads();   // all reads of sHid done; reuse it for edge weights

        // ---- + b2 -> sHid region (fp32 ew) ----
        #pragma unroll
        for (int nt = 0; nt < 4; nt++) {
            int col = (nh * 4 + nt) * 8 + 2 * tg;
            float bb0 = sBias[128 + col], bb1 = sBias[128 + col + 1];
            float2 lo = make_float2(C2[nt][0] + bb0, C2[nt][1] + bb1);
            float2 hi = make_float2(C2[nt][2] + bb0, C2[nt][3] + bb1);
            *(float2*)(sHid + (mt * 16 + g) * 132 + col)     = lo;
            *(float2*)(sHid + (mt * 16 + g + 8) * 132 + col) = hi;
        }
        __syncthreads();

        // ---- epilogue: 4 threads per edge ----
        {
            int e_l = tid >> 2, cg = tid & 3;
            int e = tile * ETILE + e_l;
            int s_ = src[e], g_ = tgt[e];
            const float4* hd4 = (const float4*)(g_hd + (size_t)s_ * ND + cg * 16);
            float4* m4 = (float4*)(g_msg + (size_t)e * ND + cg * 16);
            const float* ew = sHid + e_l * 132 + cg * 16;
            const float* avp = sBias + 192 + cg * 16;
            float sc = 0.f;
            #pragma unroll
            for (int i = 0; i < 4; i++) {
                float4 w = *(const float4*)(ew + 4 * i);
                float4 h = hd4[i];
                float4 m = make_float4(h.x * w.x, h.y * w.y, h.z * w.z, h.w * w.w);
                m4[i] = m;
                sc = fmaf(m.x, avp[4 * i],     sc);
                sc = fmaf(m.y, avp[4 * i + 1], sc);
                sc = fmaf(m.z, avp[4 * i + 2], sc);
                sc = fmaf(m.w, avp[4 * i + 3], sc);
            }
            sc += __shfl_xor_sync(0xffffffffu, sc, 1);
            sc += __shfl_xor_sync(0xffffffffu, sc, 2);
            if (cg == 0) {
                g_score[e] = sc;
                atomicMaxF(&g_segmax[g_], sc);
            }
        }
        __syncthreads();
    }
}

// ============ fused softmax-weight + aggregation (unnormalized) ============
__global__ void k_edge_agg(const int* __restrict__ ei) {
    long gid = blockIdx.x * (long)blockDim.x + threadIdx.x;
    if (gid >= (long)NE * 16) return;
    int e = (int)(gid >> 4);
    int part = (int)gid & 15;
    int g = ei[NE + e];
    float ex = expf(g_score[e] - g_segmax[g]);
    if (part == 0) atomicAdd(&g_denom[g], ex);
    int c = part * 4;
    float4 m = *(const float4*)(g_msg + (size_t)e * ND + c);
    m.x *= ex; m.y *= ex; m.z *= ex; m.w *= ex;
    atomicAdd((float4*)(g_agg + (size_t)g * ND + c), m);
}

// ============ node update MLP (4 nodes per warp iter) ============
#define NODE_SMEM_F (8192 + 8192 + 128 + 64 + 8 * 256 + 8 * 512)
__global__ void __launch_bounds__(256) k_node(
        const float* __restrict__ W1, const float* __restrict__ b1,
        const float* __restrict__ W2, const float* __restrict__ b2) {
    extern __shared__ float sm[];
    float* sW1   = sm;
    float* sW2   = sm + 8192;
    float* sb1   = sm + 16384;
    float* sb2   = sm + 16512;
    float* sAggT = sm + 16576;
    float* sHidT = sm + 16576 + 2048;
    int t = threadIdx.x;
    for (int i = t; i < 8192; i += 256) sW1[i] = W1[i];
    for (int i = t; i < 8192; i += 256) sW2[i] = W2[i];
    if (t < 128) sb1[t] = b1[t];
    if (t < 64) sb2[t] = b2[t];
    __syncthreads();

    int w = t >> 5, l = t & 31;
    float* agT  = sAggT + w * 256;
    float* hidT = sHidT + w * 512;
    const int NGRP = NN / 4;
    int grp = blockIdx.x * 8 + w;
    int ngrp = gridDim.x * 8;

    for (int gi = grp; gi < NGRP; gi += ngrp) {
        int n0 = gi * 4;
        #pragma unroll
        for (int i = 0; i < 4; i++) {
            float dn = g_denom[n0 + i];
            float invd = dn > 0.f ? 1.f / dn : 0.f;
            float2 v = *(const float2*)(g_agg + (size_t)(n0 + i) * ND + 2 * l);
            agT[(2 * l) * 4 + i]     = v.x * invd;
            agT[(2 * l + 1) * 4 + i] = v.y * invd;
        }
        __syncwarp();

        float b;
        b = sb1[4 * l + 0]; float4 a0 = make_float4(b, b, b, b);
        b = sb1[4 * l + 1]; float4 a1 = make_float4(b, b, b, b);
        b = sb1[4 * l + 2]; float4 a2 = make_float4(b, b, b, b);
        b = sb1[4 * l + 3]; float4 a3 = make_float4(b, b, b, b);
        #pragma unroll 8
        for (int k = 0; k < 64; k++) {
            float4 e4 = *(const float4*)(agT + k * 4);
            float4 w4 = *(const float4*)(sW1 + k * 128 + 4 * l);
            a0.x = fmaf(e4.x, w4.x, a0.x); a0.y = fmaf(e4.y, w4.x, a0.y);
            a0.z = fmaf(e4.z, w4.x, a0.z); a0.w = fmaf(e4.w, w4.x, a0.w);
            a1.x = fmaf(e4.x, w4.y, a1.x); a1.y = fmaf(e4.y, w4.y, a1.y);
            a1.z = fmaf(e4.z, w4.y, a1.z); a1.w = fmaf(e4.w, w4.y, a1.w);
            a2.x = fmaf(e4.x, w4.z, a2.x); a2.y = fmaf(e4.y, w4.z, a2.y);
            a2.z = fmaf(e4.z, w4.z, a2.z); a2.w = fmaf(e4.w, w4.z, a2.w);
            a3.x = fmaf(e4.x, w4.w, a3.x); a3.y = fmaf(e4.y, w4.w, a3.y);
            a3.z = fmaf(e4.z, w4.w, a3.z); a3.w = fmaf(e4.w, w4.w, a3.w);
        }
        a0.x = tanhf(a0.x); a0.y = tanhf(a0.y); a0.z = tanhf(a0.z); a0.w = tanhf(a0.w);
        a1.x = tanhf(a1.x); a1.y = tanhf(a1.y); a1.z = tanhf(a1.z); a1.w = tanhf(a1.w);
        a2.x = tanhf(a2.x); a2.y = tanhf(a2.y); a2.z = tanhf(a2.z); a2.w = tanhf(a2.w);
        a3.x = tanhf(a3.x); a3.y = tanhf(a3.y); a3.z = tanhf(a3.z); a3.w = tanhf(a3.w);
        *(float4*)(hidT + (4 * l + 0) * 4) = a0;
        *(float4*)(hidT + (4 * l + 1) * 4) = a1;
        *(float4*)(hidT + (4 * l + 2) * 4) = a2;
        *(float4*)(hidT + (4 * l + 3) * 4) = a3;
        __syncwarp();

        b = sb2[2 * l];     float4 o0 = make_float4(b, b, b, b);
        b = sb2[2 * l + 1]; float4 o1 = make_float4(b, b, b, b);
        #pragma unroll 8
        for (int k = 0; k < 128; k++) {
            float4 h4 = *(const float4*)(hidT + k * 4);
            float2 w2 = *(const float2*)(sW2 + k * 64 + 2 * l);
            o0.x = fmaf(h4.x, w2.x, o0.x); o0.y = fmaf(h4.y, w2.x, o0.y);
            o0.z = fmaf(h4.z, w2.x, o0.z); o0.w = fmaf(h4.w, w2.x, o0.w);
            o1.x = fmaf(h4.x, w2.y, o1.x); o1.y = fmaf(h4.y, w2.y, o1.y);
            o1.z = fmaf(h4.z, w2.y, o1.z); o1.w = fmaf(h4.w, w2.y, o1.w);
        }

        #define NODE_EPI(I, O0, O1) {                                        \
            float2 hv_ = *(float2*)(g_h + (size_t)(n0 + I) * ND + 2 * l);    \
            hv_.x += (O0); hv_.y += (O1);                                    \
            *(float2*)(g_h + (size_t)(n0 + I) * ND + 2 * l) = hv_;           \
        }
        NODE_EPI(0, o0.x, o1.x)
        NODE_EPI(1, o0.y, o1.y)
        NODE_EPI(2, o0.z, o1.z)
        NODE_EPI(3, o0.w, o1.w)
        #undef NODE_EPI
        __syncwarp();
    }
}

// ---------------- pooling + final MLP ----------------
__global__ void k_pool_init() {
    int i = threadIdx.x + blockIdx.x * blockDim.x;
    if (i < NG * ND) g_pooled[i] = 0.f;
    if (i < NG) g_cnt[i] = 0;
}

__global__ void k_pool(const int* __restrict__ batch) {
    long gid = blockIdx.x * (long)blockDim.x + threadIdx.x;
    if (gid >= (long)NN * 16) return;
    int n = (int)(gid >> 4);
    int c = ((int)gid & 15) * 4;
    int b = batch[n];
    float4 v = *(const float4*)(g_h + (size_t)n * ND + c);
    atomicAdd((float4*)(g_pooled + b * ND + c), v);
    if (c == 0) atomicAdd(&g_cnt[b], 1);
}

#define FINAL_SMEM_F (8192 + 4096 + 128 + 32 + 512 + 1024)
__global__ void k_final(const float* __restrict__ W1, const float* __restrict__ b1,
                        const float* __restrict__ W2, const float* __restrict__ b2,
                        float* __restrict__ out) {
    extern __shared__ float sm[];
    float* sW1  = sm;
    float* sW2  = sm + 8192;
    float* sb1  = sm + 12288;
    float* sb2  = sm + 12416;
    float* sP   = sm + 12448;
    float* sHid = sm + 12960;
    int t = threadIdx.x;
    for (int i = t; i < 8192; i += 256) sW1[i] = W1[i];
    for (int i = t; i < 4096; i += 256) sW2[i] = W2[i];
    if (t < 128) sb1[t] = b1[t];
    if (t < 32) sb2[t] = b2[t];
    __syncthreads();

    int w = t >> 5, l = t & 31;
    int g = blockIdx.x * 8 + w;
    if (g >= NG) return;
    float inv = 1.f / (float)max(g_cnt[g], 1);
    float* pw   = sP + w * 64;
    float* hidw = sHid + w * 128;
    float2 pv = *(const float2*)(g_pooled + g * ND + 2 * l);
    pw[2 * l] = pv.x * inv;
    pw[2 * l + 1] = pv.y * inv;
    __syncwarp();
    float4 acc = *(const float4*)(sb1 + 4 * l);
    #pragma unroll 8
    for (int k = 0; k < 64; k++) {
        float a = pw[k];
        float4 wv = *(const float4*)(sW1 + k * 128 + 4 * l);
        acc.x = fmaf(a, wv.x, acc.x);
        acc.y = fmaf(a, wv.y, acc.y);
        acc.z = fmaf(a, wv.z, acc.z);
        acc.w = fmaf(a, wv.w, acc.w);
    }
    acc.x = tanhf(acc.x); acc.y = tanhf(acc.y);
    acc.z = tanhf(acc.z); acc.w = tanhf(acc.w);
    *(float4*)(hidw + 4 * l) = acc;
    __syncwarp();
    float o = sb2[l];
    #pragma unroll 8
    for (int k = 0; k < 128; k += 4) {
        float4 hv = *(const float4*)(hidw + k);
        o = fmaf(hv.x, sW2[(k    ) * 32 + l], o);
        o = fmaf(hv.y, sW2[(k + 1) * 32 + l], o);
        o = fmaf(hv.z, sW2[(k + 2) * 32 + l], o);
        o = fmaf(hv.w, sW2[(k + 3) * 32 + l], o);
    }
    out[g * OD + l] = o;
}

// ---------------- launch ----------------
extern "C" void kernel_launch(void* const* d_in, const int* in_sizes, int n_in,
                              void* d_out, int out_size) {
    const float *x, *ea, *Wd, *fW1, *fb1, *fW2, *fb2, *av;
    const float *oW1, *ob1, *oW2, *ob2, *nW1, *nb1, *nW2, *nb2;
    const int *ei, *batch;

    if (in_sizes[2] == 2 * NE) {
        x   = (const float*)d_in[0];  ea  = (const float*)d_in[1];
        ei  = (const int*)  d_in[2];  batch = (const int*)d_in[3];
        Wd  = (const float*)d_in[4];
        fW1 = (const float*)d_in[5];  fb1 = (const float*)d_in[6];
        fW2 = (const float*)d_in[7];  fb2 = (const float*)d_in[8];
        av  = (const float*)d_in[9];
        oW1 = (const float*)d_in[10]; ob1 = (const float*)d_in[11];
        oW2 = (const float*)d_in[12]; ob2 = (const float*)d_in[13];
        nW1 = (const float*)d_in[14]; nb1 = (const float*)d_in[15];
        nW2 = (const float*)d_in[16]; nb2 = (const float*)d_in[17];
    } else {
        x   = (const float*)d_in[0];  ea  = (const float*)d_in[1];
        Wd  = (const float*)d_in[2];
        fW1 = (const float*)d_in[3];  fb1 = (const float*)d_in[4];
        fW2 = (const float*)d_in[5];  fb2 = (const float*)d_in[6];
        av  = (const float*)d_in[7];
        oW1 = (const float*)d_in[8];  ob1 = (const float*)d_in[9];
        oW2 = (const float*)d_in[10]; ob2 = (const float*)d_in[11];
        nW1 = (const float*)d_in[12]; nb1 = (const float*)d_in[13];
        nW2 = (const float*)d_in[14]; nb2 = (const float*)d_in[15];
        ei  = (const int*)d_in[16];   batch = (const int*)d_in[17];
    }

    cudaFuncSetAttribute(k_edge_mma, cudaFuncAttributeMaxDynamicSharedMemorySize,
                         EDGE_SMEM_F * 4);
    cudaFuncSetAttribute(k_node, cudaFuncAttributeMaxDynamicSharedMemorySize,
                         NODE_SMEM_F * 4);
    cudaFuncSetAttribute(k_final, cudaFuncAttributeMaxDynamicSharedMemorySize,
                         FINAL_SMEM_F * 4);

    k_copy_h<<<(NN * ND + 255) / 256, 256>>>(x);

    for (int i = 0; i < NL; i++) {
        k_dense<<<1480, 256>>>(Wd + i * ND * ND);
        k_init_layer<<<1480, 256>>>();
        k_edge_mma<<<296, 256, EDGE_SMEM_F * 4>>>(
            ea, ei,
            fW1 + i * ED * NH, fb1 + i * NH,
            fW2 + i * NH * ND, fb2 + i * ND,
            av + i * ND);
        k_edge_agg<<<(int)(((long)NE * 16 + 255) / 256), 256>>>(ei);
        k_node<<<296, 256, NODE_SMEM_F * 4>>>(
            oW1 + i * ND * NH, ob1 + i * NH,
            oW2 + i * NH * ND, ob2 + i * ND);
    }

    k_pool_init<<<(NG * ND + 255) / 256, 256>>>();
    k_pool<<<(int)(((long)NN * 16 + 255) / 256), 256>>>(batch);
    k_final<<<16, 256, FINAL_SMEM_F * 4>>>(nW1, nb1, nW2, nb2, (float*)d_out);
}

// round 5
// speedup vs baseline: 3.9259x; 1.2311x over previous
#include <cuda_runtime.h>
#include <math.h>
#include <stdint.h>

#define NN 50000
#define NE 800000
#define ND 64
#define ED 32
#define NH 128
#define OD 32
#define NL 3
#define NG 128
#define ETILE 64
#define NTILES (NE / ETILE)        // 12500
#define NTILES_N ((NN + 63) / 64)  // 782 (last tile has 16 rows)

// ---------------- device scratch ----------------
__device__ float g_h[NN * ND];
__device__ float g_hd[NN * ND];
__device__ float g_denom[NN];
__device__ float g_agg[NN * ND];
__device__ float g_pooled[NG * ND];
__device__ int   g_cnt[NG];

__device__ __forceinline__ uint32_t f2tf(float f) {
    uint32_t r;
    asm("cvt.rna.tf32.f32 %0, %1;" : "=r"(r) : "f"(f));
    return r;
}

__device__ __forceinline__ void mma_tf32(float* c, const uint32_t* a, const uint32_t* b) {
    asm volatile(
        "mma.sync.aligned.m16n8k8.row.col.f32.tf32.tf32.f32 "
        "{%0,%1,%2,%3}, {%4,%5,%6,%7}, {%8,%9}, {%0,%1,%2,%3};"
        : "+f"(c[0]), "+f"(c[1]), "+f"(c[2]), "+f"(c[3])
        : "r"(a[0]), "r"(a[1]), "r"(a[2]), "r"(a[3]), "r"(b[0]), "r"(b[1]));
}

// ---------------- trivial kernels ----------------
__global__ void k_copy_h(const float* __restrict__ x) {
    int i = blockIdx.x * blockDim.x + threadIdx.x;
    if (i < NN * ND) g_h[i] = x[i];
}

// hd = h @ Wd ; also zero g_agg / g_denom for this layer
__global__ void k_dense(const float* __restrict__ Wd) {
    __shared__ float sW[64 * 64];
    __shared__ float sh[4][64];
    int t = threadIdx.x;
    {   // zero agg + denom
        int i = blockIdx.x * blockDim.x + t;
        int stride = gridDim.x * blockDim.x;
        for (int j = i; j < NN * ND; j += stride) g_agg[j] = 0.f;
        for (int j = i; j < NN; j += stride) g_denom[j] = 0.f;
    }
    for (int i = t; i < 64 * 64; i += 256) sW[i] = Wd[i];
    __syncthreads();
    int r = t >> 6, c = t & 63;
    for (int base = blockIdx.x * 4; base < NN; base += gridDim.x * 4) {
        int n = base + r;
        if (n < NN) sh[r][c] = g_h[n * ND + c];
        __syncthreads();
        if (n < NN) {
            float acc = 0.f;
            #pragma unroll
            for (int k = 0; k < 64; k++) acc = fmaf(sh[r][k], sW[k * 64 + c], acc);
            g_hd[n * ND + c] = acc;
        }
        __syncthreads();
    }
}

// ============ edge MLP via warp-level tf32 MMA, fused direct-exp aggregation ============
// smem floats: sA[64*36]=2304 @0 | sHid[64*132]=8448 @2304 | sB1[4096] @10752 |
//              sB2[8192] @14848 | sBias[256] @23040  -> total 23296 f
#define O_A 0
#define O_HID 2304
#define O_B1 10752
#define O_B2 14848
#define O_BIAS 23040
#define EDGE_SMEM_F 23296

__global__ void __launch_bounds__(256) k_edge_mma(
        const float* __restrict__ ea, const int* __restrict__ ei,
        const float* __restrict__ W1, const float* __restrict__ b1,
        const float* __restrict__ W2, const float* __restrict__ b2,
        const float* __restrict__ av) {
    extern __shared__ float sm[];
    float* sA   = sm + O_A;
    float* sHid = sm + O_HID;
    float* sB1  = sm + O_B1;
    float* sB2  = sm + O_B2;
    float* sBias= sm + O_BIAS;
    int tid = threadIdx.x;
    int lane = tid & 31, wid = tid >> 5;
    int g = lane >> 2, tg = lane & 3;

    // pack W1 fragments
    for (int idx = tid; idx < 4 * 16 * 32; idx += 256) {
        int l = idx & 31, nt = (idx >> 5) & 15, ks = idx >> 9;
        int kk = ks * 8 + (l & 3), nn = nt * 8 + (l >> 2);
        float2 v;
        v.x = __uint_as_float(f2tf(W1[kk * NH + nn]));
        v.y = __uint_as_float(f2tf(W1[(kk + 4) * NH + nn]));
        *(float2*)(sB1 + (size_t)idx * 2) = v;
    }
    // pack W2 fragments
    for (int idx = tid; idx < 16 * 8 * 32; idx += 256) {
        int l = idx & 31, nt = (idx >> 5) & 7, ks = idx >> 8;
        int kk = ks * 8 + (l & 3), nn = nt * 8 + (l >> 2);
        float2 v;
        v.x = __uint_as_float(f2tf(W2[kk * ND + nn]));
        v.y = __uint_as_float(f2tf(W2[(kk + 4) * ND + nn]));
        *(float2*)(sB2 + (size_t)idx * 2) = v;
    }
    if (tid < 128) sBias[tid] = b1[tid];
    if (tid < 64)  sBias[128 + tid] = b2[tid];
    if (tid < 64)  sBias[192 + tid] = av[tid];
    __syncthreads();

    const int* src = ei;
    const int* tgt = ei + NE;
    int mt = wid & 3;
    int nh = wid >> 2;

    for (int tile = blockIdx.x; tile < NTILES; tile += gridDim.x) {
        // ---- load A tile (64 edges x 32), tf32, stride 36 ----
        {
            int e_l = tid >> 2, q = tid & 3;
            const float4* rp = (const float4*)(ea + (size_t)(tile * ETILE + e_l) * ED + q * 8);
            float4 v0 = rp[0], v1 = rp[1];
            v0.x = __uint_as_float(f2tf(v0.x)); v0.y = __uint_as_float(f2tf(v0.y));
            v0.z = __uint_as_float(f2tf(v0.z)); v0.w = __uint_as_float(f2tf(v0.w));
            v1.x = __uint_as_float(f2tf(v1.x)); v1.y = __uint_as_float(f2tf(v1.y));
            v1.z = __uint_as_float(f2tf(v1.z)); v1.w = __uint_as_float(f2tf(v1.w));
            *(float4*)(sA + e_l * 36 + q * 8)     = v0;
            *(float4*)(sA + e_l * 36 + q * 8 + 4) = v1;
        }
        __syncthreads();

        // ---- GEMM1: hid[64x128] = A @ W1 ----
        float C1[8][4];
        #pragma unroll
        for (int nt = 0; nt < 8; nt++)
            C1[nt][0] = C1[nt][1] = C1[nt][2] = C1[nt][3] = 0.f;
        #pragma unroll
        for (int ks = 0; ks < 4; ks++) {
            uint32_t a[4];
            int r0 = (mt * 16 + g) * 36 + ks * 8 + tg;
            a[0] = __float_as_uint(sA[r0]);
            a[1] = __float_as_uint(sA[r0 + 8 * 36]);
            a[2] = __float_as_uint(sA[r0 + 4]);
            a[3] = __float_as_uint(sA[r0 + 8 * 36 + 4]);
            #pragma unroll
            for (int nt = 0; nt < 8; nt++) {
                int ntg = nh * 8 + nt;
                float2 bf = *(const float2*)(sB1 + (ks * 16 + ntg) * 64 + 2 * lane);
                uint32_t b[2] = { __float_as_uint(bf.x), __float_as_uint(bf.y) };
                mma_tf32(C1[nt], a, b);
            }
        }
        // ---- bias + tanh -> sHid tf32 ----
        #pragma unroll
        for (int nt = 0; nt < 8; nt++) {
            int col = (nh * 8 + nt) * 8 + 2 * tg;
            float bb0 = sBias[col], bb1 = sBias[col + 1];
            float2 lo, hi;
            lo.x = __uint_as_float(f2tf(tanhf(C1[nt][0] + bb0)));
            lo.y = __uint_as_float(f2tf(tanhf(C1[nt][1] + bb1)));
            hi.x = __uint_as_float(f2tf(tanhf(C1[nt][2] + bb0)));
            hi.y = __uint_as_float(f2tf(tanhf(C1[nt][3] + bb1)));
            *(float2*)(sHid + (mt * 16 + g) * 132 + col)     = lo;
            *(float2*)(sHid + (mt * 16 + g + 8) * 132 + col) = hi;
        }
        __syncthreads();

        // ---- GEMM2: ew[64x64] = hid @ W2 ----
        float C2[4][4];
        #pragma unroll
        for (int nt = 0; nt < 4; nt++)
            C2[nt][0] = C2[nt][1] = C2[nt][2] = C2[nt][3] = 0.f;
        #pragma unroll
        for (int ks = 0; ks < 16; ks++) {
            uint32_t a[4];
            int r0 = (mt * 16 + g) * 132 + ks * 8 + tg;
            a[0] = __float_as_uint(sHid[r0]);
            a[1] = __float_as_uint(sHid[r0 + 8 * 132]);
            a[2] = __float_as_uint(sHid[r0 + 4]);
            a[3] = __float_as_uint(sHid[r0 + 8 * 132 + 4]);
            #pragma unroll
            for (int nt = 0; nt < 4; nt++) {
                int ntg = nh * 4 + nt;
                float2 bf = *(const float2*)(sB2 + (ks * 8 + ntg) * 64 + 2 * lane);
                uint32_t b[2] = { __float_as_uint(bf.x), __float_as_uint(bf.y) };
                mma_tf32(C2[nt], a, b);
            }
        }
        __syncthreads();

        // ---- + b2 -> sHid (fp32 ew) ----
        #pragma unroll
        for (int nt = 0; nt < 4; nt++) {
            int col = (nh * 4 + nt) * 8 + 2 * tg;
            float bb0 = sBias[128 + col], bb1 = sBias[128 + col + 1];
            *(float2*)(sHid + (mt * 16 + g) * 132 + col)     = make_float2(C2[nt][0] + bb0, C2[nt][1] + bb1);
            *(float2*)(sHid + (mt * 16 + g + 8) * 132 + col) = make_float2(C2[nt][2] + bb0, C2[nt][3] + bb1);
        }
        __syncthreads();

        // ---- epilogue: 4 threads/edge; direct-exp fused aggregation ----
        {
            int e_l = tid >> 2, cg = tid & 3;
            int e = tile * ETILE + e_l;
            int s_ = src[e], g_ = tgt[e];
            const float4* hd4 = (const float4*)(g_hd + (size_t)s_ * ND + cg * 16);
            const float* ew = sHid + e_l * 132 + cg * 16;
            const float* avp = sBias + 192 + cg * 16;
            float4 m[4];
            float sc = 0.f;
            #pragma unroll
            for (int i = 0; i < 4; i++) {
                float4 w = *(const float4*)(ew + 4 * i);
                float4 h = hd4[i];
                m[i] = make_float4(h.x * w.x, h.y * w.y, h.z * w.z, h.w * w.w);
                sc = fmaf(m[i].x, avp[4 * i],     sc);
                sc = fmaf(m[i].y, avp[4 * i + 1], sc);
                sc = fmaf(m[i].z, avp[4 * i + 2], sc);
                sc = fmaf(m[i].w, avp[4 * i + 3], sc);
            }
            sc += __shfl_xor_sync(0xffffffffu, sc, 1);
            sc += __shfl_xor_sync(0xffffffffu, sc, 2);
            float ex = expf(sc);   // scores are O(0.1): direct exp == max-subtracted softmax
            if (cg == 0) atomicAdd(&g_denom[g_], ex);
            float* aggp = g_agg + (size_t)g_ * ND + cg * 16;
            #pragma unroll
            for (int i = 0; i < 4; i++) {
                float4 v = make_float4(m[i].x * ex, m[i].y * ex, m[i].z * ex, m[i].w * ex);
                atomicAdd((float4*)(aggp + 4 * i), v);
            }
        }
        // no trailing sync needed: next-iter A store is fenced by the post-A-store sync
    }
}

// ============ node update MLP via tf32 MMA (64 nodes/tile) ============
// smem floats: sA[64*68]=4352 @0 | sHid[64*132]=8448 @4352 | sB1[8192] @12800 |
//              sB2[8192] @20992 | sBias[192] @29184 -> 29376 f
#define N_O_A 0
#define N_O_HID 4352
#define N_O_B1 12800
#define N_O_B2 20992
#define N_O_BIAS 29184
#define NODE_SMEM_F 29376

__global__ void __launch_bounds__(256) k_node_mma(
        const float* __restrict__ W1, const float* __restrict__ b1,
        const float* __restrict__ W2, const float* __restrict__ b2,
        const int* __restrict__ batch, int do_pool) {
    extern __shared__ float sm[];
    float* sA   = sm + N_O_A;     // [64][68]
    float* sHid = sm + N_O_HID;   // [64][132]
    float* sB1  = sm + N_O_B1;
    float* sB2  = sm + N_O_B2;
    float* sBias= sm + N_O_BIAS;
    int tid = threadIdx.x;
    int lane = tid & 31, wid = tid >> 5;
    int g = lane >> 2, tg = lane & 3;

    // pack W1 [64x128] fragments
    for (int idx = tid; idx < 8 * 16 * 32; idx += 256) {
        int l = idx & 31, nt = (idx >> 5) & 15, ks = idx >> 9;
        int kk = ks * 8 + (l & 3), nn = nt * 8 + (l >> 2);
        float2 v;
        v.x = __uint_as_float(f2tf(W1[kk * NH + nn]));
        v.y = __uint_as_float(f2tf(W1[(kk + 4) * NH + nn]));
        *(float2*)(sB1 + (size_t)idx * 2) = v;
    }
    // pack W2 [128x64] fragments
    for (int idx = tid; idx < 16 * 8 * 32; idx += 256) {
        int l = idx & 31, nt = (idx >> 5) & 7, ks = idx >> 8;
        int kk = ks * 8 + (l & 3), nn = nt * 8 + (l >> 2);
        float2 v;
        v.x = __uint_as_float(f2tf(W2[kk * ND + nn]));
        v.y = __uint_as_float(f2tf(W2[(kk + 4) * ND + nn]));
        *(float2*)(sB2 + (size_t)idx * 2) = v;
    }
    if (tid < 128) sBias[tid] = b1[tid];
    if (tid < 64)  sBias[128 + tid] = b2[tid];
    __syncthreads();

    int mt = wid & 3;
    int nh = wid >> 2;

    for (int tile = blockIdx.x; tile < NTILES_N; tile += gridDim.x) {
        int base = tile * 64;
        int nrows = NN - base; if (nrows > 64) nrows = 64;
        // ---- load A = agg/denom (tf32), stride 68 ----
        {
            int e_l = tid >> 2, q = tid & 3;
            float4 v0 = make_float4(0.f, 0.f, 0.f, 0.f), v1 = v0, v2 = v0, v3 = v0;
            if (e_l < nrows) {
                int n = base + e_l;
                float dn = g_denom[n];
                float invd = dn > 0.f ? 1.f / dn : 0.f;
                const float4* rp = (const float4*)(g_agg + (size_t)n * ND + q * 16);
                v0 = rp[0]; v1 = rp[1]; v2 = rp[2]; v3 = rp[3];
                v0.x *= invd; v0.y *= invd; v0.z *= invd; v0.w *= invd;
                v1.x *= invd; v1.y *= invd; v1.z *= invd; v1.w *= invd;
                v2.x *= invd; v2.y *= invd; v2.z *= invd; v2.w *= invd;
                v3.x *= invd; v3.y *= invd; v3.z *= invd; v3.w *= invd;
            }
            #define TF4(v) { v.x = __uint_as_float(f2tf(v.x)); v.y = __uint_as_float(f2tf(v.y)); \
                             v.z = __uint_as_float(f2tf(v.z)); v.w = __uint_as_float(f2tf(v.w)); }
            TF4(v0) TF4(v1) TF4(v2) TF4(v3)
            #undef TF4
            float* dst = sA + e_l * 68 + q * 16;
            *(float4*)(dst)      = v0;
            *(float4*)(dst + 4)  = v1;
            *(float4*)(dst + 8)  = v2;
            *(float4*)(dst + 12) = v3;
        }
        __syncthreads();

        // ---- GEMM1: hid[64x128] = A @ W1 (K=64) ----
        float C1[8][4];
        #pragma unroll
        for (int nt = 0; nt < 8; nt++)
            C1[nt][0] = C1[nt][1] = C1[nt][2] = C1[nt][3] = 0.f;
        #pragma unroll
        for (int ks = 0; ks < 8; ks++) {
            uint32_t a[4];
            int r0 = (mt * 16 + g) * 68 + ks * 8 + tg;
            a[0] = __float_as_uint(sA[r0]);
            a[1] = __float_as_uint(sA[r0 + 8 * 68]);
            a[2] = __float_as_uint(sA[r0 + 4]);
            a[3] = __float_as_uint(sA[r0 + 8 * 68 + 4]);
            #pragma unroll
            for (int nt = 0; nt < 8; nt++) {
                int ntg = nh * 8 + nt;
                float2 bf = *(const float2*)(sB1 + (ks * 16 + ntg) * 64 + 2 * lane);
                uint32_t b[2] = { __float_as_uint(bf.x), __float_as_uint(bf.y) };
                mma_tf32(C1[nt], a, b);
            }
        }
        #pragma unroll
        for (int nt = 0; nt < 8; nt++) {
            int col = (nh * 8 + nt) * 8 + 2 * tg;
            float bb0 = sBias[col], bb1 = sBias[col + 1];
            float2 lo, hi;
            lo.x = __uint_as_float(f2tf(tanhf(C1[nt][0] + bb0)));
            lo.y = __uint_as_float(f2tf(tanhf(C1[nt][1] + bb1)));
            hi.x = __uint_as_float(f2tf(tanhf(C1[nt][2] + bb0)));
            hi.y = __uint_as_float(f2tf(tanhf(C1[nt][3] + bb1)));
            *(float2*)(sHid + (mt * 16 + g) * 132 + col)     = lo;
            *(float2*)(sHid + (mt * 16 + g + 8) * 132 + col) = hi;
        }
        __syncthreads();

        // ---- GEMM2: delta[64x64] = hid @ W2 (K=128) ----
        float C2[4][4];
        #pragma unroll
        for (int nt = 0; nt < 4; nt++)
            C2[nt][0] = C2[nt][1] = C2[nt][2] = C2[nt][3] = 0.f;
        #pragma unroll
        for (int ks = 0; ks < 16; ks++) {
            uint32_t a[4];
            int r0 = (mt * 16 + g) * 132 + ks * 8 + tg;
            a[0] = __float_as_uint(sHid[r0]);
            a[1] = __float_as_uint(sHid[r0 + 8 * 132]);
            a[2] = __float_as_uint(sHid[r0 + 4]);
            a[3] = __float_as_uint(sHid[r0 + 8 * 132 + 4]);
            #pragma unroll
            for (int nt = 0; nt < 4; nt++) {
                int ntg = nh * 4 + nt;
                float2 bf = *(const float2*)(sB2 + (ks * 8 + ntg) * 64 + 2 * lane);
                uint32_t b[2] = { __float_as_uint(bf.x), __float_as_uint(bf.y) };
                mma_tf32(C2[nt], a, b);
            }
        }
        __syncthreads();

        #pragma unroll
        for (int nt = 0; nt < 4; nt++) {
            int col = (nh * 4 + nt) * 8 + 2 * tg;
            float bb0 = sBias[128 + col], bb1 = sBias[128 + col + 1];
            *(float2*)(sHid + (mt * 16 + g) * 132 + col)     = make_float2(C2[nt][0] + bb0, C2[nt][1] + bb1);
            *(float2*)(sHid + (mt * 16 + g + 8) * 132 + col) = make_float2(C2[nt][2] + bb0, C2[nt][3] + bb1);
        }
        __syncthreads();

        // ---- epilogue: h += delta, optional fused pooling ----
        {
            int e_l = tid >> 2, cg = tid & 3;
            if (e_l < nrows) {
                int n = base + e_l;
                float* hp = g_h + (size_t)n * ND + cg * 16;
                const float* dw = sHid + e_l * 132 + cg * 16;
                float4 hv[4];
                #pragma unroll
                for (int i = 0; i < 4; i++) {
                    float4 h = *(float4*)(hp + 4 * i);
                    float4 d = *(const float4*)(dw + 4 * i);
                    hv[i] = make_float4(h.x + d.x, h.y + d.y, h.z + d.z, h.w + d.w);
                    *(float4*)(hp + 4 * i) = hv[i];
                }
                if (do_pool) {
                    int b = batch[n];
                    float* pp = g_pooled + b * ND + cg * 16;
                    #pragma unroll
                    for (int i = 0; i < 4; i++)
                        atomicAdd((float4*)(pp + 4 * i), hv[i]);
                    if (cg == 0) atomicAdd(&g_cnt[b], 1);
                }
            }
        }
    }
}

// ---------------- pooling init + final MLP ----------------
__global__ void k_pool_init() {
    int i = threadIdx.x + blockIdx.x * blockDim.x;
    if (i < NG * ND) g_pooled[i] = 0.f;
    if (i < NG) g_cnt[i] = 0;
}

#define FINAL_SMEM_F (8192 + 4096 + 128 + 32 + 512 + 1024)
__global__ void k_final(const float* __restrict__ W1, const float* __restrict__ b1,
                        const float* __restrict__ W2, const float* __restrict__ b2,
                        float* __restrict__ out) {
    extern __shared__ float sm[];
    float* sW1  = sm;
    float* sW2  = sm + 8192;
    float* sb1  = sm + 12288;
    float* sb2  = sm + 12416;
    float* sP   = sm + 12448;
    float* sHid = sm + 12960;
    int t = threadIdx.x;
    for (int i = t; i < 8192; i += 256) sW1[i] = W1[i];
    for (int i = t; i < 4096; i += 256) sW2[i] = W2[i];
    if (t < 128) sb1[t] = b1[t];
    if (t < 32) sb2[t] = b2[t];
    __syncthreads();

    int w = t >> 5, l = t & 31;
    int g = blockIdx.x * 8 + w;
    if (g >= NG) return;
    float inv = 1.f / (float)max(g_cnt[g], 1);
    float* pw   = sP + w * 64;
    float* hidw = sHid + w * 128;
    float2 pv = *(const float2*)(g_pooled + g * ND + 2 * l);
    pw[2 * l] = pv.x * inv;
    pw[2 * l + 1] = pv.y * inv;
    __syncwarp();
    float4 acc = *(const float4*)(sb1 + 4 * l);
    #pragma unroll 8
    for (int k = 0; k < 64; k++) {
        float a = pw[k];
        float4 wv = *(const float4*)(sW1 + k * 128 + 4 * l);
        acc.x = fmaf(a, wv.x, acc.x);
        acc.y = fmaf(a, wv.y, acc.y);
        acc.z = fmaf(a, wv.z, acc.z);
        acc.w = fmaf(a, wv.w, acc.w);
    }
    acc.x = tanhf(acc.x); acc.y = tanhf(acc.y);
    acc.z = tanhf(acc.z); acc.w = tanhf(acc.w);
    *(float4*)(hidw + 4 * l) = acc;
    __syncwarp();
    float o = sb2[l];
    #pragma unroll 8
    for (int k = 0; k < 128; k += 4) {
        float4 hv = *(const float4*)(hidw + k);
        o = fmaf(hv.x, sW2[(k    ) * 32 + l], o);
        o = fmaf(hv.y, sW2[(k + 1) * 32 + l], o);
        o = fmaf(hv.z, sW2[(k + 2) * 32 + l], o);
        o = fmaf(hv.w, sW2[(k + 3) * 32 + l], o);
    }
    out[g * OD + l] = o;
}

// ---------------- launch ----------------
extern "C" void kernel_launch(void* const* d_in, const int* in_sizes, int n_in,
                              void* d_out, int out_size) {
    const float *x, *ea, *Wd, *fW1, *fb1, *fW2, *fb2, *av;
    const float *oW1, *ob1, *oW2, *ob2, *nW1, *nb1, *nW2, *nb2;
    const int *ei, *batch;

    if (in_sizes[2] == 2 * NE) {
        x   = (const float*)d_in[0];  ea  = (const float*)d_in[1];
        ei  = (const int*)  d_in[2];  batch = (const int*)d_in[3];
        Wd  = (const float*)d_in[4];
        fW1 = (const float*)d_in[5];  fb1 = (const float*)d_in[6];
        fW2 = (const float*)d_in[7];  fb2 = (const float*)d_in[8];
        av  = (const float*)d_in[9];
        oW1 = (const float*)d_in[10]; ob1 = (const float*)d_in[11];
        oW2 = (const float*)d_in[12]; ob2 = (const float*)d_in[13];
        nW1 = (const float*)d_in[14]; nb1 = (const float*)d_in[15];
        nW2 = (const float*)d_in[16]; nb2 = (const float*)d_in[17];
    } else {
        x   = (const float*)d_in[0];  ea  = (const float*)d_in[1];
        Wd  = (const float*)d_in[2];
        fW1 = (const float*)d_in[3];  fb1 = (const float*)d_in[4];
        fW2 = (const float*)d_in[5];  fb2 = (const float*)d_in[6];
        av  = (const float*)d_in[7];
        oW1 = (const float*)d_in[8];  ob1 = (const float*)d_in[9];
        oW2 = (const float*)d_in[10]; ob2 = (const float*)d_in[11];
        nW1 = (const float*)d_in[12]; nb1 = (const float*)d_in[13];
        nW2 = (const float*)d_in[14]; nb2 = (const float*)d_in[15];
        ei  = (const int*)d_in[16];   batch = (const int*)d_in[17];
    }

    cudaFuncSetAttribute(k_edge_mma, cudaFuncAttributeMaxDynamicSharedMemorySize,
                         EDGE_SMEM_F * 4);
    cudaFuncSetAttribute(k_node_mma, cudaFuncAttributeMaxDynamicSharedMemorySize,
                         NODE_SMEM_F * 4);
    cudaFuncSetAttribute(k_final, cudaFuncAttributeMaxDynamicSharedMemorySize,
                         FINAL_SMEM_F * 4);

    k_copy_h<<<(NN * ND + 255) / 256, 256>>>(x);
    k_pool_init<<<(NG * ND + 255) / 256, 256>>>();

    for (int i = 0; i < NL; i++) {
        k_dense<<<1480, 256>>>(Wd + i * ND * ND);
        k_edge_mma<<<296, 256, EDGE_SMEM_F * 4>>>(
            ea, ei,
            fW1 + i * ED * NH, fb1 + i * NH,
            fW2 + i * NH * ND, fb2 + i * ND,
            av + i * ND);
        k_node_mma<<<296, 256, NODE_SMEM_F * 4>>>(
            oW1 + i * ND * NH, ob1 + i * NH,
            oW2 + i * NH * ND, ob2 + i * ND,
            batch, (i == NL - 1) ? 1 : 0);
    }

    k_final<<<16, 256, FINAL_SMEM_F * 4>>>(nW1, nb1, nW2, nb2, (float*)d_out);
}

// round 6
// speedup vs baseline: 5.3295x; 1.3575x over previous
#include <cuda_runtime.h>
#include <cuda_bf16.h>
#include <math.h>
#include <stdint.h>

#define NN 50000
#define NE 800000
#define ND 64
#define ED 32
#define NH 128
#define OD 32
#define NL 3
#define NG 128
#define ETILE 64
#define NTILES (NE / ETILE)        // 12500
#define NTILES_N ((NN + 63) / 64)  // 782

// ---------------- device scratch ----------------
__device__ float g_h[NN * ND];
__device__ float g_hd[NN * ND];
__device__ float g_denom[NN];
__device__ float g_agg[NN * ND];
__device__ float g_pooled[NG * ND];
__device__ int   g_cnt[NG];

__device__ __forceinline__ uint32_t f2bf2(float lo, float hi) {
    uint32_t r;
    asm("cvt.rn.bf16x2.f32 %0, %1, %2;" : "=r"(r) : "f"(hi), "f"(lo));
    return r;
}

__device__ __forceinline__ void mma_bf16(float* c, uint32_t a0, uint32_t a1,
                                         uint32_t a2, uint32_t a3,
                                         uint32_t b0, uint32_t b1) {
    asm volatile(
        "mma.sync.aligned.m16n8k16.row.col.f32.bf16.bf16.f32 "
        "{%0,%1,%2,%3}, {%4,%5,%6,%7}, {%8,%9}, {%0,%1,%2,%3};"
        : "+f"(c[0]), "+f"(c[1]), "+f"(c[2]), "+f"(c[3])
        : "r"(a0), "r"(a1), "r"(a2), "r"(a3), "r"(b0), "r"(b1));
}

// ---------------- trivial kernels ----------------
__global__ void k_copy_h(const float* __restrict__ x) {
    int i = blockIdx.x * blockDim.x + threadIdx.x;
    if (i < NN * ND) g_h[i] = x[i];
}

// hd = h @ Wd ; also zero g_agg / g_denom for this layer
__global__ void k_dense(const float* __restrict__ Wd) {
    __shared__ float sW[64 * 64];
    __shared__ float sh[4][64];
    int t = threadIdx.x;
    {
        int i = blockIdx.x * blockDim.x + t;
        int stride = gridDim.x * blockDim.x;
        for (int j = i; j < NN * ND; j += stride) g_agg[j] = 0.f;
        for (int j = i; j < NN; j += stride) g_denom[j] = 0.f;
    }
    for (int i = t; i < 64 * 64; i += 256) sW[i] = Wd[i];
    __syncthreads();
    int r = t >> 6, c = t & 63;
    for (int base = blockIdx.x * 4; base < NN; base += gridDim.x * 4) {
        int n = base + r;
        if (n < NN) sh[r][c] = g_h[n * ND + c];
        __syncthreads();
        if (n < NN) {
            float acc = 0.f;
            #pragma unroll
            for (int k = 0; k < 64; k++) acc = fmaf(sh[r][k], sW[k * 64 + c], acc);
            g_hd[n * ND + c] = acc;
        }
        __syncthreads();
    }
}

// ============ edge MLP via bf16 m16n8k16 MMA, fused direct-exp aggregation ============
// smem bytes: sA[64*80B]=5120 @0 | sHid 17408 @5120 (bf16 [64][136] / fp32 ew [64][68]) |
//             sB1 8192 @22528 | sB2 16384 @30720 | sBias 1024 @47104 -> 48128 B
#define E_O_A 0
#define E_O_HID 5120
#define E_O_B1 22528
#define E_O_B2 30720
#define E_O_BIAS 47104
#define EDGE_SMEM_B 48128

__global__ void __launch_bounds__(256) k_edge_mma(
        const float* __restrict__ ea, const int* __restrict__ ei,
        const float* __restrict__ W1, const float* __restrict__ b1,
        const float* __restrict__ W2, const float* __restrict__ b2,
        const float* __restrict__ av) {
    extern __shared__ char smem[];
    uint32_t* sB1u = (uint32_t*)(smem + E_O_B1);
    uint32_t* sB2u = (uint32_t*)(smem + E_O_B2);
    float* sBias = (float*)(smem + E_O_BIAS);
    int tid = threadIdx.x;
    int lane = tid & 31, wid = tid >> 5;
    int g = lane >> 2, tg = lane & 3;

    // pack W1 fragments (2 ks x 16 ntg)
    for (int idx = tid; idx < 2 * 16 * 32; idx += 256) {
        int l = idx & 31, nt = (idx >> 5) & 15, ks = idx >> 9;
        int gg = l >> 2, tt = l & 3;
        int n = nt * 8 + gg, k0 = ks * 16 + 2 * tt;
        uint2 v;
        v.x = f2bf2(W1[k0 * NH + n], W1[(k0 + 1) * NH + n]);
        v.y = f2bf2(W1[(k0 + 8) * NH + n], W1[(k0 + 9) * NH + n]);
        *(uint2*)(sB1u + (size_t)((ks * 16 + nt) * 64 + 2 * l)) = v;
    }
    // pack W2 fragments (8 ks x 8 ntg)
    for (int idx = tid; idx < 8 * 8 * 32; idx += 256) {
        int l = idx & 31, nt = (idx >> 5) & 7, ks = idx >> 8;
        int gg = l >> 2, tt = l & 3;
        int n = nt * 8 + gg, k0 = ks * 16 + 2 * tt;
        uint2 v;
        v.x = f2bf2(W2[k0 * ND + n], W2[(k0 + 1) * ND + n]);
        v.y = f2bf2(W2[(k0 + 8) * ND + n], W2[(k0 + 9) * ND + n]);
        *(uint2*)(sB2u + (size_t)((ks * 8 + nt) * 64 + 2 * l)) = v;
    }
    if (tid < 128) sBias[tid] = b1[tid];
    if (tid < 64)  sBias[128 + tid] = b2[tid];
    if (tid < 64)  sBias[192 + tid] = av[tid];
    __syncthreads();

    const int* src = ei;
    const int* tgt = ei + NE;
    int mt = wid & 3;
    int nh = wid >> 2;

    for (int tile = blockIdx.x; tile < NTILES; tile += gridDim.x) {
        // ---- load A tile: 64 edges x 32 f32 -> bf16 [64][40] (80 B rows) ----
        {
            int e_l = tid >> 2, q = tid & 3;
            const float4* rp = (const float4*)(ea + (size_t)(tile * ETILE + e_l) * ED + q * 8);
            float4 v0 = rp[0], v1 = rp[1];
            uint4 p;
            p.x = f2bf2(v0.x, v0.y); p.y = f2bf2(v0.z, v0.w);
            p.z = f2bf2(v1.x, v1.y); p.w = f2bf2(v1.z, v1.w);
            *(uint4*)(smem + E_O_A + e_l * 80 + q * 16) = p;
        }
        __syncthreads();

        // ---- GEMM1: hid[64x128] = A @ W1 (K=32, 2 ks) ----
        float C1[8][4];
        #pragma unroll
        for (int nt = 0; nt < 8; nt++)
            C1[nt][0] = C1[nt][1] = C1[nt][2] = C1[nt][3] = 0.f;
        #pragma unroll
        for (int ks = 0; ks < 2; ks++) {
            const char* ab = smem + E_O_A + (mt * 16 + g) * 80 + ks * 32 + 4 * tg;
            uint32_t a0 = *(const uint32_t*)(ab);
            uint32_t a1 = *(const uint32_t*)(ab + 8 * 80);
            uint32_t a2 = *(const uint32_t*)(ab + 16);
            uint32_t a3 = *(const uint32_t*)(ab + 8 * 80 + 16);
            #pragma unroll
            for (int nt = 0; nt < 8; nt++) {
                int ntg = nh * 8 + nt;
                uint2 bf = *(const uint2*)(sB1u + (ks * 16 + ntg) * 64 + 2 * lane);
                mma_bf16(C1[nt], a0, a1, a2, a3, bf.x, bf.y);
            }
        }
        // ---- bias + tanh -> sHid bf16 [64][136] (272 B rows) ----
        #pragma unroll
        for (int nt = 0; nt < 8; nt++) {
            int col = (nh * 8 + nt) * 8 + 2 * tg;
            float bb0 = sBias[col], bb1 = sBias[col + 1];
            uint32_t lo = f2bf2(tanhf(C1[nt][0] + bb0), tanhf(C1[nt][1] + bb1));
            uint32_t hi = f2bf2(tanhf(C1[nt][2] + bb0), tanhf(C1[nt][3] + bb1));
            *(uint32_t*)(smem + E_O_HID + (mt * 16 + g) * 272 + col * 2)     = lo;
            *(uint32_t*)(smem + E_O_HID + (mt * 16 + g + 8) * 272 + col * 2) = hi;
        }
        __syncthreads();

        // ---- GEMM2: ew[64x64] = hid @ W2 (K=128, 8 ks) ----
        float C2[4][4];
        #pragma unroll
        for (int nt = 0; nt < 4; nt++)
            C2[nt][0] = C2[nt][1] = C2[nt][2] = C2[nt][3] = 0.f;
        #pragma unroll
        for (int ks = 0; ks < 8; ks++) {
            const char* ab = smem + E_O_HID + (mt * 16 + g) * 272 + ks * 32 + 4 * tg;
            uint32_t a0 = *(const uint32_t*)(ab);
            uint32_t a1 = *(const uint32_t*)(ab + 8 * 272);
            uint32_t a2 = *(const uint32_t*)(ab + 16);
            uint32_t a3 = *(const uint32_t*)(ab + 8 * 272 + 16);
            #pragma unroll
            for (int nt = 0; nt < 4; nt++) {
                int ntg = nh * 4 + nt;
                uint2 bf = *(const uint2*)(sB2u + (ks * 8 + ntg) * 64 + 2 * lane);
                mma_bf16(C2[nt], a0, a1, a2, a3, bf.x, bf.y);
            }
        }
        __syncthreads();

        // ---- + b2 -> ew fp32 [64][68] over sHid region ----
        {
            float* ewp = (float*)(smem + E_O_HID);
            #pragma unroll
            for (int nt = 0; nt < 4; nt++) {
                int col = (nh * 4 + nt) * 8 + 2 * tg;
                float bb0 = sBias[128 + col], bb1 = sBias[128 + col + 1];
                *(float2*)(ewp + (mt * 16 + g) * 68 + col)     = make_float2(C2[nt][0] + bb0, C2[nt][1] + bb1);
                *(float2*)(ewp + (mt * 16 + g + 8) * 68 + col) = make_float2(C2[nt][2] + bb0, C2[nt][3] + bb1);
            }
        }
        __syncthreads();

        // ---- epilogue: 4 threads/edge; direct-exp fused aggregation ----
        {
            int e_l = tid >> 2, cg = tid & 3;
            int e = tile * ETILE + e_l;
            int s_ = src[e], g_ = tgt[e];
            const float4* hd4 = (const float4*)(g_hd + (size_t)s_ * ND + cg * 16);
            const float* ew = (const float*)(smem + E_O_HID) + e_l * 68 + cg * 16;
            const float* avp = sBias + 192 + cg * 16;
            float4 m[4];
            float sc = 0.f;
            #pragma unroll
            for (int i = 0; i < 4; i++) {
                float4 w = *(const float4*)(ew + 4 * i);
                float4 h = hd4[i];
                m[i] = make_float4(h.x * w.x, h.y * w.y, h.z * w.z, h.w * w.w);
                sc = fmaf(m[i].x, avp[4 * i],     sc);
                sc = fmaf(m[i].y, avp[4 * i + 1], sc);
                sc = fmaf(m[i].z, avp[4 * i + 2], sc);
                sc = fmaf(m[i].w, avp[4 * i + 3], sc);
            }
            sc += __shfl_xor_sync(0xffffffffu, sc, 1);
            sc += __shfl_xor_sync(0xffffffffu, sc, 2);
            float ex = expf(sc);   // scores O(0.1): direct exp == max-subtracted softmax
            if (cg == 0) atomicAdd(&g_denom[g_], ex);
            float* aggp = g_agg + (size_t)g_ * ND + cg * 16;
            #pragma unroll
            for (int i = 0; i < 4; i++) {
                float4 v = make_float4(m[i].x * ex, m[i].y * ex, m[i].z * ex, m[i].w * ex);
                atomicAdd((float4*)(aggp + 4 * i), v);
            }
        }
    }
}

// ============ node update MLP via bf16 MMA (64 nodes/tile) ============
// smem bytes: sA[64*144B]=9216 @0 | sHid 17408 @9216 | sB1 16384 @26624 |
//             sB2 16384 @43008 | sBias 1024 @59392 -> 60416 B
#define N_O_A 0
#define N_O_HID 9216
#define N_O_B1 26624
#define N_O_B2 43008
#define N_O_BIAS 59392
#define NODE_SMEM_B 60416

__global__ void __launch_bounds__(256) k_node_mma(
        const float* __restrict__ W1, const float* __restrict__ b1,
        const float* __restrict__ W2, const float* __restrict__ b2,
        const int* __restrict__ batch, int do_pool) {
    extern __shared__ char smem[];
    uint32_t* sB1u = (uint32_t*)(smem + N_O_B1);
    uint32_t* sB2u = (uint32_t*)(smem + N_O_B2);
    float* sBias = (float*)(smem + N_O_BIAS);
    int tid = threadIdx.x;
    int lane = tid & 31, wid = tid >> 5;
    int g = lane >> 2, tg = lane & 3;

    // pack W1 [64x128] fragments (4 ks x 16 ntg)
    for (int idx = tid; idx < 4 * 16 * 32; idx += 256) {
        int l = idx & 31, nt = (idx >> 5) & 15, ks = idx >> 9;
        int gg = l >> 2, tt = l & 3;
        int n = nt * 8 + gg, k0 = ks * 16 + 2 * tt;
        uint2 v;
        v.x = f2bf2(W1[k0 * NH + n], W1[(k0 + 1) * NH + n]);
        v.y = f2bf2(W1[(k0 + 8) * NH + n], W1[(k0 + 9) * NH + n]);
        *(uint2*)(sB1u + (size_t)((ks * 16 + nt) * 64 + 2 * l)) = v;
    }
    // pack W2 [128x64] fragments (8 ks x 8 ntg)
    for (int idx = tid; idx < 8 * 8 * 32; idx += 256) {
        int l = idx & 31, nt = (idx >> 5) & 7, ks = idx >> 8;
        int gg = l >> 2, tt = l & 3;
        int n = nt * 8 + gg, k0 = ks * 16 + 2 * tt;
        uint2 v;
        v.x = f2bf2(W2[k0 * ND + n], W2[(k0 + 1) * ND + n]);
        v.y = f2bf2(W2[(k0 + 8) * ND + n], W2[(k0 + 9) * ND + n]);
        *(uint2*)(sB2u + (size_t)((ks * 8 + nt) * 64 + 2 * l)) = v;
    }
    if (tid < 128) sBias[tid] = b1[tid];
    if (tid < 64)  sBias[128 + tid] = b2[tid];
    __syncthreads();

    int mt = wid & 3;
    int nh = wid >> 2;

    for (int tile = blockIdx.x; tile < NTILES_N; tile += gridDim.x) {
        int base = tile * 64;
        int nrows = NN - base; if (nrows > 64) nrows = 64;
        // ---- load A = agg/denom -> bf16 [64][72] (144 B rows) ----
        {
            int e_l = tid >> 2, q = tid & 3;
            float4 v0 = make_float4(0.f,0.f,0.f,0.f), v1 = v0, v2 = v0, v3 = v0;
            if (e_l < nrows) {
                int n = base + e_l;
                float dn = g_denom[n];
                float invd = dn > 0.f ? 1.f / dn : 0.f;
                const float4* rp = (const float4*)(g_agg + (size_t)n * ND + q * 16);
                v0 = rp[0]; v1 = rp[1]; v2 = rp[2]; v3 = rp[3];
                v0.x *= invd; v0.y *= invd; v0.z *= invd; v0.w *= invd;
                v1.x *= invd; v1.y *= invd; v1.z *= invd; v1.w *= invd;
                v2.x *= invd; v2.y *= invd; v2.z *= invd; v2.w *= invd;
                v3.x *= invd; v3.y *= invd; v3.z *= invd; v3.w *= invd;
            }
            uint4 pA, pB;
            pA.x = f2bf2(v0.x, v0.y); pA.y = f2bf2(v0.z, v0.w);
            pA.z = f2bf2(v1.x, v1.y); pA.w = f2bf2(v1.z, v1.w);
            pB.x = f2bf2(v2.x, v2.y); pB.y = f2bf2(v2.z, v2.w);
            pB.z = f2bf2(v3.x, v3.y); pB.w = f2bf2(v3.z, v3.w);
            *(uint4*)(smem + N_O_A + e_l * 144 + q * 32)      = pA;
            *(uint4*)(smem + N_O_A + e_l * 144 + q * 32 + 16) = pB;
        }
        __syncthreads();

        // ---- GEMM1: hid = A @ W1 (K=64, 4 ks) ----
        float C1[8][4];
        #pragma unroll
        for (int nt = 0; nt < 8; nt++)
            C1[nt][0] = C1[nt][1] = C1[nt][2] = C1[nt][3] = 0.f;
        #pragma unroll
        for (int ks = 0; ks < 4; ks++) {
            const char* ab = smem + N_O_A + (mt * 16 + g) * 144 + ks * 32 + 4 * tg;
            uint32_t a0 = *(const uint32_t*)(ab);
            uint32_t a1 = *(const uint32_t*)(ab + 8 * 144);
            uint32_t a2 = *(const uint32_t*)(ab + 16);
            uint32_t a3 = *(const uint32_t*)(ab + 8 * 144 + 16);
            #pragma unroll
            for (int nt = 0; nt < 8; nt++) {
                int ntg = nh * 8 + nt;
                uint2 bf = *(const uint2*)(sB1u + (ks * 16 + ntg) * 64 + 2 * lane);
                mma_bf16(C1[nt], a0, a1, a2, a3, bf.x, bf.y);
            }
        }
        #pragma unroll
        for (int nt = 0; nt < 8; nt++) {
            int col = (nh * 8 + nt) * 8 + 2 * tg;
            float bb0 = sBias[col], bb1 = sBias[col + 1];
            uint32_t lo = f2bf2(tanhf(C1[nt][0] + bb0), tanhf(C1[nt][1] + bb1));
            uint32_t hi = f2bf2(tanhf(C1[nt][2] + bb0), tanhf(C1[nt][3] + bb1));
            *(uint32_t*)(smem + N_O_HID + (mt * 16 + g) * 272 + col * 2)     = lo;
            *(uint32_t*)(smem + N_O_HID + (mt * 16 + g + 8) * 272 + col * 2) = hi;
        }
        __syncthreads();

        // ---- GEMM2: delta = hid @ W2 (K=128, 8 ks) ----
        float C2[4][4];
        #pragma unroll
        for (int nt = 0; nt < 4; nt++)
            C2[nt][0] = C2[nt][1] = C2[nt][2] = C2[nt][3] = 0.f;
        #pragma unroll
        for (int ks = 0; ks < 8; ks++) {
            const char* ab = smem + N_O_HID + (mt * 16 + g) * 272 + ks * 32 + 4 * tg;
            uint32_t a0 = *(const uint32_t*)(ab);
            uint32_t a1 = *(const uint32_t*)(ab + 8 * 272);
            uint32_t a2 = *(const uint32_t*)(ab + 16);
            uint32_t a3 = *(const uint32_t*)(ab + 8 * 272 + 16);
            #pragma unroll
            for (int nt = 0; nt < 4; nt++) {
                int ntg = nh * 4 + nt;
                uint2 bf = *(const uint2*)(sB2u + (ks * 8 + ntg) * 64 + 2 * lane);
                mma_bf16(C2[nt], a0, a1, a2, a3, bf.x, bf.y);
            }
        }
        __syncthreads();

        {
            float* dwp = (float*)(smem + N_O_HID);
            #pragma unroll
            for (int nt = 0; nt < 4; nt++) {
                int col = (nh * 4 + nt) * 8 + 2 * tg;
                float bb0 = sBias[128 + col], bb1 = sBias[128 + col + 1];
                *(float2*)(dwp + (mt * 16 + g) * 68 + col)     = make_float2(C2[nt][0] + bb0, C2[nt][1] + bb1);
                *(float2*)(dwp + (mt * 16 + g + 8) * 68 + col) = make_float2(C2[nt][2] + bb0, C2[nt][3] + bb1);
            }
        }
        __syncthreads();

        // ---- epilogue: h += delta, optional fused pooling ----
        {
            int e_l = tid >> 2, cg = tid & 3;
            if (e_l < nrows) {
                int n = base + e_l;
                float* hp = g_h + (size_t)n * ND + cg * 16;
                const float* dw = (const float*)(smem + N_O_HID) + e_l * 68 + cg * 16;
                float4 hv[4];
                #pragma unroll
                for (int i = 0; i < 4; i++) {
                    float4 h = *(float4*)(hp + 4 * i);
                    float4 d = *(const float4*)(dw + 4 * i);
                    hv[i] = make_float4(h.x + d.x, h.y + d.y, h.z + d.z, h.w + d.w);
                    *(float4*)(hp + 4 * i) = hv[i];
                }
                if (do_pool) {
                    int b = batch[n];
                    float* pp = g_pooled + b * ND + cg * 16;
                    #pragma unroll
                    for (int i = 0; i < 4; i++)
                        atomicAdd((float4*)(pp + 4 * i), hv[i]);
                    if (cg == 0) atomicAdd(&g_cnt[b], 1);
                }
            }
        }
    }
}

// ---------------- pooling init + final MLP ----------------
__global__ void k_pool_init() {
    int i = threadIdx.x + blockIdx.x * blockDim.x;
    if (i < NG * ND) g_pooled[i] = 0.f;
    if (i < NG) g_cnt[i] = 0;
}

#define FINAL_SMEM_F (8192 + 4096 + 128 + 32 + 512 + 1024)
__global__ void k_final(const float* __restrict__ W1, const float* __restrict__ b1,
                        const float* __restrict__ W2, const float* __restrict__ b2,
                        float* __restrict__ out) {
    extern __shared__ float sm[];
    float* sW1  = sm;
    float* sW2  = sm + 8192;
    float* sb1  = sm + 12288;
    float* sb2  = sm + 12416;
    float* sP   = sm + 12448;
    float* sHid = sm + 12960;
    int t = threadIdx.x;
    for (int i = t; i < 8192; i += 256) sW1[i] = W1[i];
    for (int i = t; i < 4096; i += 256) sW2[i] = W2[i];
    if (t < 128) sb1[t] = b1[t];
    if (t < 32) sb2[t] = b2[t];
    __syncthreads();

    int w = t >> 5, l = t & 31;
    int g = blockIdx.x * 8 + w;
    if (g >= NG) return;
    float inv = 1.f / (float)max(g_cnt[g], 1);
    float* pw   = sP + w * 64;
    float* hidw = sHid + w * 128;
    float2 pv = *(const float2*)(g_pooled + g * ND + 2 * l);
    pw[2 * l] = pv.x * inv;
    pw[2 * l + 1] = pv.y * inv;
    __syncwarp();
    float4 acc = *(const float4*)(sb1 + 4 * l);
    #pragma unroll 8
    for (int k = 0; k < 64; k++) {
        float a = pw[k];
        float4 wv = *(const float4*)(sW1 + k * 128 + 4 * l);
        acc.x = fmaf(a, wv.x, acc.x);
        acc.y = fmaf(a, wv.y, acc.y);
        acc.z = fmaf(a, wv.z, acc.z);
        acc.w = fmaf(a, wv.w, acc.w);
    }
    acc.x = tanhf(acc.x); acc.y = tanhf(acc.y);
    acc.z = tanhf(acc.z); acc.w = tanhf(acc.w);
    *(float4*)(hidw + 4 * l) = acc;
    __syncwarp();
    float o = sb2[l];
    #pragma unroll 8
    for (int k = 0; k < 128; k += 4) {
        float4 hv = *(const float4*)(hidw + k);
        o = fmaf(hv.x, sW2[(k    ) * 32 + l], o);
        o = fmaf(hv.y, sW2[(k + 1) * 32 + l], o);
        o = fmaf(hv.z, sW2[(k + 2) * 32 + l], o);
        o = fmaf(hv.w, sW2[(k + 3) * 32 + l], o);
    }
    out[g * OD + l] = o;
}

// ---------------- launch ----------------
extern "C" void kernel_launch(void* const* d_in, const int* in_sizes, int n_in,
                              void* d_out, int out_size) {
    const float *x, *ea, *Wd, *fW1, *fb1, *fW2, *fb2, *av;
    const float *oW1, *ob1, *oW2, *ob2, *nW1, *nb1, *nW2, *nb2;
    const int *ei, *batch;

    if (in_sizes[2] == 2 * NE) {
        x   = (const float*)d_in[0];  ea  = (const float*)d_in[1];
        ei  = (const int*)  d_in[2];  batch = (const int*)d_in[3];
        Wd  = (const float*)d_in[4];
        fW1 = (const float*)d_in[5];  fb1 = (const float*)d_in[6];
        fW2 = (const float*)d_in[7];  fb2 = (const float*)d_in[8];
        av  = (const float*)d_in[9];
        oW1 = (const float*)d_in[10]; ob1 = (const float*)d_in[11];
        oW2 = (const float*)d_in[12]; ob2 = (const float*)d_in[13];
        nW1 = (const float*)d_in[14]; nb1 = (const float*)d_in[15];
        nW2 = (const float*)d_in[16]; nb2 = (const float*)d_in[17];
    } else {
        x   = (const float*)d_in[0];  ea  = (const float*)d_in[1];
        Wd  = (const float*)d_in[2];
        fW1 = (const float*)d_in[3];  fb1 = (const float*)d_in[4];
        fW2 = (const float*)d_in[5];  fb2 = (const float*)d_in[6];
        av  = (const float*)d_in[7];
        oW1 = (const float*)d_in[8];  ob1 = (const float*)d_in[9];
        oW2 = (const float*)d_in[10]; ob2 = (const float*)d_in[11];
        nW1 = (const float*)d_in[12]; nb1 = (const float*)d_in[13];
        nW2 = (const float*)d_in[14]; nb2 = (const float*)d_in[15];
        ei  = (const int*)d_in[16];   batch = (const int*)d_in[17];
    }

    cudaFuncSetAttribute(k_edge_mma, cudaFuncAttributeMaxDynamicSharedMemorySize,
                         EDGE_SMEM_B);
    cudaFuncSetAttribute(k_node_mma, cudaFuncAttributeMaxDynamicSharedMemorySize,
                         NODE_SMEM_B);
    cudaFuncSetAttribute(k_final, cudaFuncAttributeMaxDynamicSharedMemorySize,
                         FINAL_SMEM_F * 4);

    k_copy_h<<<(NN * ND + 255) / 256, 256>>>(x);
    k_pool_init<<<(NG * ND + 255) / 256, 256>>>();

    for (int i = 0; i < NL; i++) {
        k_dense<<<1480, 256>>>(Wd + i * ND * ND);
        k_edge_mma<<<592, 256, EDGE_SMEM_B>>>(
            ea, ei,
            fW1 + i * ED * NH, fb1 + i * NH,
            fW2 + i * NH * ND, fb2 + i * ND,
            av + i * ND);
        k_node_mma<<<444, 256, NODE_SMEM_B>>>(
            oW1 + i * ND * NH, ob1 + i * NH,
            oW2 + i * NH * ND, ob2 + i * ND,
            batch, (i == NL - 1) ? 1 : 0);
    }

    k_final<<<16, 256, FINAL_SMEM_F * 4>>>(nW1, nb1, nW2, nb2, (float*)d_out);
}